// round 11
// baseline (speedup 1.0000x reference)
#include <cuda_runtime.h>
#include <cuda_bf16.h>
#include <math.h>
#include <stdint.h>

// ---------------- problem constants ----------------
#define Dn    64
#define Pn    32
#define NMC   16
#define NG    512           // Pn*NMC
#define NOBS  2048
#define CAP   52            // max m handled by bge_mid (l <= 51)
#define TRI_CAP 1378        // CAP*(CAP+1)/2
// output layout (floats)
#define OFF_RECONS 0
#define OFF_LOGP   4096
#define OFF_QZ     4128
#define OFF_QMU    6176
#define OFF_QLV    8224
#define OFF_GHARD  10272
#define OFF_ZNEW   141344

// ---------------- device scratch ----------------
static __device__ double             g_xbard[Dn];
static __device__ float              g_Rpart[16 * 4096];
static __device__ float              g_R[Dn * Dn];
static __device__ float              g_probs[Pn * Dn * Dn];
static __device__ unsigned long long g_cols[NG * Dn];
static __device__ unsigned long long g_colsh[Pn * Dn];
static __device__ double             g_ns[NG * Dn];
static __device__ double             g_nsh[Pn * Dn];
static __device__ double             g_logp[NG];
static __device__ double             g_w[NG];
static __device__ float              g_B[Pn * Dn * Dn];
static __device__ float              g_grads[Pn * Dn * Dn * 2];
static __device__ float              g_Kmat[Pn * Pn];
static __device__ unsigned int       g_keys[4];
static __device__ double             g_lgtab[64];
static __device__ double             g_logitpe;
static __device__ float              g_h0[Pn * 20];

// ---------------- threefry2x32 (JAX-exact) ----------------
__device__ __forceinline__ void tf2x32(unsigned k0, unsigned k1,
                                       unsigned x0, unsigned x1,
                                       unsigned &o0, unsigned &o1) {
    unsigned ks0 = k0, ks1 = k1, ks2 = k0 ^ k1 ^ 0x1BD11BDAu;
    x0 += ks0; x1 += ks1;
#define TFR(r) { x0 += x1; x1 = __funnelshift_l(x1, x1, r); x1 ^= x0; }
    TFR(13) TFR(15) TFR(26) TFR(6)   x0 += ks1; x1 += ks2 + 1u;
    TFR(17) TFR(29) TFR(16) TFR(24)  x0 += ks2; x1 += ks0 + 2u;
    TFR(13) TFR(15) TFR(26) TFR(6)   x0 += ks0; x1 += ks1 + 3u;
    TFR(17) TFR(29) TFR(16) TFR(24)  x0 += ks1; x1 += ks2 + 4u;
    TFR(13) TFR(15) TFR(26) TFR(6)   x0 += ks2; x1 += ks0 + 5u;
#undef TFR
    o0 = x0; o1 = x1;
}

__device__ __forceinline__ unsigned jax_bits32(unsigned k0, unsigned k1, unsigned idx) {
    unsigned o0, o1;
    tf2x32(k0, k1, 0u, idx, o0, o1);
    return o0 ^ o1;
}

__device__ __forceinline__ float u01f(unsigned b) {
    return __uint_as_float((b >> 9) | 0x3f800000u) - 1.0f;
}

__device__ __forceinline__ float jax_normal(unsigned bits) {
    const float lo = -0.99999994f;
    float f = u01f(bits);
    float u = fmaxf(lo, fmaf(f, 2.0f, lo));
    float w = -log1pf(-u * u);
    float p;
    if (w < 5.0f) {
        w -= 2.5f;
        p = 2.81022636e-08f;
        p = fmaf(p, w, 3.43273939e-07f);
        p = fmaf(p, w, -3.5233877e-06f);
        p = fmaf(p, w, -4.39150654e-06f);
        p = fmaf(p, w, 0.00021858087f);
        p = fmaf(p, w, -0.00125372503f);
        p = fmaf(p, w, -0.00417768164f);
        p = fmaf(p, w, 0.246640727f);
        p = fmaf(p, w, 1.50140941f);
    } else {
        w = sqrtf(w) - 3.0f;
        p = -0.000200214257f;
        p = fmaf(p, w, 0.000100950558f);
        p = fmaf(p, w, 0.00134934322f);
        p = fmaf(p, w, -0.00367342844f);
        p = fmaf(p, w, 0.00573950773f);
        p = fmaf(p, w, -0.0076224613f);
        p = fmaf(p, w, 0.00943887047f);
        p = fmaf(p, w, 1.00167406f);
        p = fmaf(p, w, 2.83297682f);
    }
    return 1.4142135381698608f * (p * u);
}

// ---------------- launch 1: scores (+init +xbar) ----------------
__global__ void scores_kernel(const float* __restrict__ z,
                              const float* __restrict__ zgt,
                              const int* __restrict__ seed_ptr) {
    __shared__ double sx[64];
    int p = blockIdx.x >> 6, i = blockIdx.x & 63, j = threadIdx.x;
    if (blockIdx.x < 64) {
        int col = blockIdx.x;
        double a = 0.0;
        int n0 = j * 32;
        for (int n = n0; n < n0 + 32; n++) a += (double)zgt[n * 64 + col];
        sx[j] = a;
        __syncthreads();
        for (int st = 32; st > 0; st >>= 1) {
            if (j < st) sx[j] += sx[j + st];
            __syncthreads();
        }
        if (j == 0) g_xbard[col] = sx[0] / 2048.0;
    }
    if (blockIdx.x == 0) {
        if (j == 0) {
            unsigned seed = (unsigned)seed_ptr[0];
            unsigned a0, a1, b0, b1;
            tf2x32(0u, seed, 0u, 0u, a0, a1);
            tf2x32(0u, seed, 0u, 1u, b0, b1);   // sk
            unsigned c0, c1, d0, d1;
            tf2x32(a0, a1, 0u, 0u, c0, c1);
            tf2x32(a0, a1, 0u, 1u, d0, d1);     // rk
            g_keys[0] = b0; g_keys[1] = b1;
            g_keys[2] = d0; g_keys[3] = d1;
            double pe = 4.0 / 63.0;
            g_logitpe = log(pe) - log1p(-pe);
        }
        const double LOG_PI   = 1.1447298858494001741;
        const double LOG_HALF = -0.6931471805599453094;
        double l = (double)j;
        g_lgtab[j] = -0.5 * log(2049.0)
                   + lgamma(0.5 * (2051.0 + l)) - lgamma(0.5 * (3.0 + l))
                   - 1024.0 * LOG_PI
                   + 0.5 * (3.0 + 2.0 * l) * LOG_HALF;
    }
    const float* zp = z + p * 8192;
    double acc = 0.0;
    for (int k = 0; k < 64; k++)
        acc += (double)zp[(i * 64 + k) * 2] * (double)zp[(j * 64 + k) * 2 + 1];
    float sc = (float)acc;
    float tl = 0.2f * sc;
    float pr = (i == j) ? 0.f : (0.5f * tanhf(0.5f * tl) + 0.5f);  // XLA logistic
    g_probs[p * 4096 + i * 64 + j] = pr;
}

// ---------------- launch 2: R tile partials (16 blocks x 256) ----------------
__global__ void Rtile_kernel(const float* __restrict__ zgt) {
    __shared__ float xs[128 * 64];
    int tid = threadIdx.x;
    int nb = blockIdx.x * 128;
    for (int idx = tid; idx < 128 * 64; idx += 256) {
        int n = idx >> 6, c = idx & 63;
        xs[idx] = zgt[(nb + n) * 64 + c] - (float)g_xbard[c];
    }
    __syncthreads();
    int i0 = (tid >> 4) << 2, j0 = (tid & 15) << 2;
    float acc[4][4];
#pragma unroll
    for (int r = 0; r < 4; r++)
#pragma unroll
        for (int c = 0; c < 4; c++) acc[r][c] = 0.f;
    for (int n = 0; n < 128; n++) {
        float4 a = *reinterpret_cast<const float4*>(&xs[n * 64 + i0]);
        float4 b = *reinterpret_cast<const float4*>(&xs[n * 64 + j0]);
        float ar[4] = {a.x, a.y, a.z, a.w};
        float br[4] = {b.x, b.y, b.z, b.w};
#pragma unroll
        for (int r = 0; r < 4; r++)
#pragma unroll
            for (int c = 0; c < 4; c++) acc[r][c] = fmaf(ar[r], br[c], acc[r][c]);
    }
    float* out = g_Rpart + blockIdx.x * 4096;
#pragma unroll
    for (int r = 0; r < 4; r++)
#pragma unroll
        for (int c = 0; c < 4; c++) out[(i0 + r) * 64 + (j0 + c)] = acc[r][c];
}

// ---------------- launch 3: bernoulli (+R finalize in blocks 0..15) ----------------
__global__ void __launch_bounds__(256) bern_kernel() {
    if (blockIdx.x < 16) {
        int idx = blockIdx.x * 256 + threadIdx.x;   // 0..4095
        int i = idx >> 6, jj = idx & 63;
        double s = 0.0;
        for (int b = 0; b < 16; b++) s += (double)g_Rpart[b * 4096 + idx];
        s += (2048.0 / 2049.0) * g_xbard[i] * g_xbard[jj];
        if (i == jj) s += 0.5;
        g_R[idx] = (float)s;
    }
    int gid = blockIdx.x * 256 + threadIdx.x;   // 262144 = 32768 cols * 8
    int part = gid & 7;
    int col = gid >> 3;                         // (p*16+s)*64 + j
    int j = col & 63, p = col >> 10;
    unsigned k0 = g_keys[0], k1 = g_keys[1];
    const float* pr = g_probs + p * 4096;
    int i0 = part * 8;
    unsigned base = (unsigned)((col >> 6) * 4096 + i0 * 64 + j);
    unsigned long long m = 0ull;
#pragma unroll
    for (int r = 0; r < 8; r++) {
        unsigned bits = jax_bits32(k0, k1, base + (unsigned)(r * 64));
        if (u01f(bits) < pr[(i0 + r) * 64 + j]) m |= 1ull << (i0 + r);
    }
    m |= __shfl_xor_sync(0xffffffffu, m, 1);
    m |= __shfl_xor_sync(0xffffffffu, m, 2);
    m |= __shfl_xor_sync(0xffffffffu, m, 4);
    if (part == 0) g_cols[col] = m;
}

// ---------------- launch 4 (profiled): BGe register path (m <= 32) ----------------
// Left-looking Cholesky, one column per lane, fully register-resident.
// Bit-identical to the smem right-looking version: row r is formed by the same
// FFMA chain acc -= U[k][r] * (U[k][j]*inv_k) in the same k order.
__global__ void __launch_bounds__(256) bge_reg_kernel(
        const unsigned long long* __restrict__ cols,
        double* __restrict__ ns, int ntask) {
    __shared__ unsigned char sidx[8][64];
    int w = threadIdx.x >> 5, lane = threadIdx.x & 31;
    int task = blockIdx.x * 8 + w;
    if (task >= ntask) return;
    unsigned long long mask = cols[task];
    int l = __popcll(mask);
    int m = l + 1;
    if (m > 32) return;                  // bge_mid / bge_big handle
    int j = task & 63;
    unsigned char* idx = sidx[w];
    if (lane == 0) {
        unsigned long long mm = mask; int c = 0;
        while (mm) { int b = __ffsll(mm) - 1; idx[c++] = (unsigned char)b; mm &= mm - 1; }
        idx[l] = (unsigned char)j;
    }
    __syncwarp();
    int idxj = idx[lane < m ? lane : (m - 1)];   // lanes >= m: duplicate last col (inert)
    float U[32], t[32];
    float logA = 0.f, lastpiv = 1.f;
#pragma unroll
    for (int r = 0; r < 32; r++) {
        if (r >= m) break;
        int idxr = __shfl_sync(0xffffffffu, idxj, r);
        float acc = g_R[idxr * 64 + idxj];
#pragma unroll
        for (int k = 0; k < r; k++) {
            float aki = __shfl_sync(0xffffffffu, U[k], r);
            acc -= aki * t[k];
        }
        U[r] = acc;
        float piv = __shfl_sync(0xffffffffu, acc, r);
        float inv = 1.0f / piv;
        t[r] = acc * inv;
        if (lane == 0) {
            if (r < m - 1) logA += logf(piv);
            else lastpiv = piv;
        }
    }
    if (lane == 0) {
        ns[task] = g_lgtab[l] - 0.5 * (double)logA
                 - 0.5 * (2051.0 + (double)l) * log((double)lastpiv);
    }
}

// ---------------- BGe mid (33 <= m <= CAP), smem rank-2, 8 warps/block ----------------
__global__ void __launch_bounds__(256) bge_mid_kernel(
        const unsigned long long* __restrict__ cols,
        double* __restrict__ ns, int ntask) {
    __shared__ float sT[8][TRI_CAP];
    __shared__ unsigned char sidx[8][64];
    int w = threadIdx.x >> 5, lane = threadIdx.x & 31;
    int task = blockIdx.x * 8 + w;
    if (task >= ntask) return;
    unsigned long long mask = cols[task];
    int l = __popcll(mask);
    int m = l + 1;
    if (m <= 32 || m > CAP) return;
    int j = task & 63;
    unsigned char* idx = sidx[w];
    if (lane == 0) {
        unsigned long long mm = mask; int c = 0;
        while (mm) { int b = __ffsll(mm) - 1; idx[c++] = (unsigned char)b; mm &= mm - 1; }
        idx[l] = (unsigned char)j;
    }
    __syncwarp();
    float* T = sT[w];
    {
        int base = 0;
        for (int a = 0; a < m; a++) {
            const float* Rrow = g_R + (int)idx[a] * 64;
            for (int b = a + lane; b < m; b += 32) T[base + b - a] = Rrow[idx[b]];
            base += m - a;
        }
    }
    __syncwarp();
    float logA = 0.f, lastpiv = 1.f;
    int basek = 0;
    int k = 0;
    if (m <= 33) {
        while (k + 1 < m) {
            int basek1 = basek + (m - k);
            float pivk = T[basek];
            float inv = 1.0f / pivk;
            float akk1 = T[basek + 1];
            int ja0 = k + 1 + lane;
            if (ja0 < m) {
                float t = T[basek + ja0 - k] * inv;
                T[basek1 + ja0 - (k + 1)] -= akk1 * t;
            }
            __syncwarp();
            float pivk1 = T[basek1];
            float inv2 = 1.0f / pivk1;
            if (lane == 0) {
                logA += logf(pivk);
                if (k + 1 < m - 1) logA += logf(pivk1);
                else lastpiv = pivk1;
            }
            int jb0 = k + 2 + lane;
            float t0 = 0.f, s0 = 0.f;
            if (jb0 < m) {
                t0 = T[basek + jb0 - k] * inv;
                s0 = T[basek1 + jb0 - k - 1] * inv2;
            }
            int bi = basek1 + (m - k - 1);
            for (int i = k + 2; i < m; i++) {
                float aki = T[basek + i - k];
                float bki = T[basek1 + i - k - 1];
                if (jb0 >= i && jb0 < m) {
                    float x = T[bi + jb0 - i];
                    x -= aki * t0;
                    x -= bki * s0;
                    T[bi + jb0 - i] = x;
                }
                bi += m - i;
            }
            basek = basek1 + (m - k - 1);
            k += 2;
            __syncwarp();
        }
    } else {
        while (k + 1 < m) {
            int basek1 = basek + (m - k);
            float pivk = T[basek];
            float inv = 1.0f / pivk;
            float akk1 = T[basek + 1];
            int ja0 = k + 1 + lane, ja1 = ja0 + 32;
            if (ja0 < m) {
                float t = T[basek + ja0 - k] * inv;
                T[basek1 + ja0 - (k + 1)] -= akk1 * t;
            }
            if (ja1 < m) {
                float t = T[basek + ja1 - k] * inv;
                T[basek1 + ja1 - (k + 1)] -= akk1 * t;
            }
            __syncwarp();
            float pivk1 = T[basek1];
            float inv2 = 1.0f / pivk1;
            if (lane == 0) {
                logA += logf(pivk);
                if (k + 1 < m - 1) logA += logf(pivk1);
                else lastpiv = pivk1;
            }
            int jb0 = k + 2 + lane, jb1 = jb0 + 32;
            float t0 = 0.f, s0 = 0.f, t1 = 0.f, s1 = 0.f;
            if (jb0 < m) {
                t0 = T[basek + jb0 - k] * inv;
                s0 = T[basek1 + jb0 - k - 1] * inv2;
            }
            if (jb1 < m) {
                t1 = T[basek + jb1 - k] * inv;
                s1 = T[basek1 + jb1 - k - 1] * inv2;
            }
            int bi = basek1 + (m - k - 1);
            for (int i = k + 2; i < m; i++) {
                float aki = T[basek + i - k];
                float bki = T[basek1 + i - k - 1];
                if (jb0 >= i && jb0 < m) {
                    float x = T[bi + jb0 - i];
                    x -= aki * t0;
                    x -= bki * s0;
                    T[bi + jb0 - i] = x;
                }
                if (jb1 >= i && jb1 < m) {
                    float x = T[bi + jb1 - i];
                    x -= aki * t1;
                    x -= bki * s1;
                    T[bi + jb1 - i] = x;
                }
                bi += m - i;
            }
            basek = basek1 + (m - k - 1);
            k += 2;
            __syncwarp();
        }
    }
    if (k < m) lastpiv = T[basek];
    if (lane == 0) {
        ns[task] = g_lgtab[l] - 0.5 * (double)logA
                 - 0.5 * (2051.0 + (double)l) * log((double)lastpiv);
    }
}

// ---------------- fallback: BGe big (m > CAP only) ----------------
__global__ void __launch_bounds__(128) bge_big_kernel(
        const unsigned long long* __restrict__ cols,
        double* __restrict__ ns, int ntask) {
    __shared__ float sT[4][2080];
    __shared__ unsigned char sidx[4][64];
    int w = threadIdx.x >> 5, lane = threadIdx.x & 31;
    int task = blockIdx.x * 4 + w;
    if (task >= ntask) return;
    unsigned long long mask = cols[task];
    int l = __popcll(mask);
    int m = l + 1;
    if (m <= CAP) return;
    int j = task & 63;
    unsigned char* idx = sidx[w];
    if (lane == 0) {
        unsigned long long mm = mask; int c = 0;
        while (mm) { int b = __ffsll(mm) - 1; idx[c++] = (unsigned char)b; mm &= mm - 1; }
        idx[l] = (unsigned char)j;
    }
    __syncwarp();
    float* T = sT[w];
    {
        int base = 0;
        for (int a = 0; a < m; a++) {
            const float* Rrow = g_R + (int)idx[a] * 64;
            for (int b = a + lane; b < m; b += 32) T[base + b - a] = Rrow[idx[b]];
            base += m - a;
        }
    }
    __syncwarp();
    float logA = 0.f, lastpiv = 1.f;
    int basek = 0;
    int k = 0;
    for (; k < m - 33; k++) {
        float piv = T[basek];
        if (lane == 0) logA += logf(piv);
        float inv = 1.0f / piv;
        int j0 = k + 1 + lane, j1 = j0 + 32;
        float t0 = T[basek + 1 + lane] * inv;
        float t1 = (j1 < m) ? T[basek + 33 + lane] * inv : 0.f;
        int bi = basek + (m - k);
        for (int i = k + 1; i < m; i++) {
            float aki = T[basek + i - k];
            if (j0 >= i)           T[bi + j0 - i] -= aki * t0;
            if (j1 >= i && j1 < m) T[bi + j1 - i] -= aki * t1;
            bi += m - i;
        }
        basek += m - k;
        __syncwarp();
    }
    for (; k < m; k++) {
        float piv = T[basek];
        if (lane == 0) {
            if (k < m - 1) logA += logf(piv);
            else lastpiv = piv;
        }
        int rem = m - 1 - k;
        if (rem > 0) {
            float inv = 1.0f / piv;
            int j0 = k + 1 + lane;
            float t0 = (lane < rem) ? T[basek + 1 + lane] * inv : 0.f;
            int bi = basek + (m - k);
            for (int i = k + 1; i < m; i++) {
                float aki = T[basek + i - k];
                if (j0 >= i && j0 < m) T[bi + j0 - i] -= aki * t0;
                bi += m - i;
            }
        }
        basek += m - k;
        __syncwarp();
    }
    if (lane == 0) {
        ns[task] = g_lgtab[l] - 0.5 * (double)logA
                 - 0.5 * (2051.0 + (double)l) * log((double)lastpiv);
    }
}

// ---------------- deterministic 64-way reduce ----------------
__global__ void reduce64_kernel(const double* __restrict__ ns, double* __restrict__ out) {
    __shared__ double s[64];
    int g = blockIdx.x, t = threadIdx.x;
    s[t] = ns[g * 64 + t];
    __syncthreads();
    for (int st = 32; st > 0; st >>= 1) {
        if (t < st) s[t] += s[t + st];
        __syncthreads();
    }
    if (t == 0) out[g] = s[0];
}

__global__ void reduce64h_kernel(const double* __restrict__ ns, float* __restrict__ out) {
    __shared__ double s[64];
    int g = blockIdx.x, t = threadIdx.x;
    s[t] = ns[g * 64 + t];
    __syncthreads();
    for (int st = 32; st > 0; st >>= 1) {
        if (t < st) s[t] += s[t + st];
        __syncthreads();
    }
    if (t == 0) out[OFF_LOGP + g] = (float)s[0];
}

// ---------------- softmax weights ----------------
__global__ void softmax_kernel() {
    int p = blockIdx.x, t = threadIdx.x;
    double v = (t < 16) ? g_logp[p * 16 + t] : -1e300;
    double mx = v;
    for (int o = 16; o > 0; o >>= 1) mx = fmax(mx, __shfl_xor_sync(0xffffffffu, mx, o));
    double e = (t < 16) ? exp(v - mx) : 0.0;
    double sm = e;
    for (int o = 16; o > 0; o >>= 1) sm += __shfl_xor_sync(0xffffffffu, sm, o);
    if (t < 16) g_w[p * 16 + t] = e / sm;
}

// ---------------- B ----------------
__global__ void B_kernel() {
    int idx = blockIdx.x * blockDim.x + threadIdx.x;
    int j = idx & 63, i = (idx >> 6) & 63, p = idx >> 12;
    float pr = g_probs[p * 4096 + i * 64 + j];
    double ws = 0.0;
    for (int s = 0; s < 16; s++)
        if ((g_cols[(p * 16 + s) * 64 + j] >> i) & 1ull) ws += g_w[p * 16 + s];
    float B = 0.f;
    if (i != j)
        B = 0.2f * ((float)ws - pr) + 0.2f * pr * (1.f - pr) * (float)g_logitpe;
    g_B[idx] = B;
}

// ---------------- grads ----------------
__global__ void gradu_kernel(const float* __restrict__ z) {
    int p = blockIdx.x >> 6, i = blockIdx.x & 63, k = threadIdx.x;
    const float* Bp = g_B + p * 4096 + i * 64;
    const float* zp = z + p * 8192;
    float acc = 0.f;
    for (int j = 0; j < 64; j++) acc = fmaf(Bp[j], zp[(j * 64 + k) * 2 + 1], acc);
    float u = zp[(i * 64 + k) * 2];
    g_grads[(blockIdx.x * 64 + k) * 2] = acc - 64.f * u;
}

__global__ void gradv_kernel(const float* __restrict__ z) {
    int p = blockIdx.x >> 6, j = blockIdx.x & 63, k = threadIdx.x;
    const float* Bp = g_B + p * 4096;
    const float* zp = z + p * 8192;
    float acc = 0.f;
    for (int i = 0; i < 64; i++) acc = fmaf(Bp[i * 64 + j], zp[(i * 64 + k) * 2], acc);
    float v = zp[(j * 64 + k) * 2 + 1];
    g_grads[((p * 64 + j) * 64 + k) * 2 + 1] = acc - 64.f * v;
}

// ---------------- SVGD ----------------
__global__ void kmat_kernel(const float* __restrict__ z) {
    int p = blockIdx.x;
    int q = threadIdx.x >> 5, lane = threadIdx.x & 31;
    const float* a = z + p * 8192;
    const float* b = z + q * 8192;
    double sq = 0.0;
    for (int t = lane; t < 8192; t += 32) {
        double d = (double)a[t] - (double)b[t];
        sq += d * d;
    }
    for (int o = 16; o > 0; o >>= 1) sq += __shfl_xor_sync(0xffffffffu, sq, o);
    if (lane == 0) g_Kmat[p * 32 + q] = (float)exp(-sq / 5.0);
}

__global__ void znew_kernel(const float* __restrict__ z, float* __restrict__ out) {
    int p = blockIdx.x;
    __shared__ float kr[32];
    __shared__ float rowsum;
    if (threadIdx.x < 32) kr[threadIdx.x] = g_Kmat[p * 32 + threadIdx.x];
    __syncthreads();
    if (threadIdx.x == 0) {
        float s = 0.f;
        for (int q = 0; q < 32; q++) s += kr[q];
        rowsum = s;
    }
    __syncthreads();
    for (int d = threadIdx.x; d < 8192; d += blockDim.x) {
        float ag = 0.f, az = 0.f;
        for (int q = 0; q < 32; q++) {
            float kk = kr[q];
            ag = fmaf(kk, g_grads[q * 8192 + d], ag);
            az = fmaf(kk, z[q * 8192 + d], az);
        }
        float zp = z[p * 8192 + d];
        float rep = (-2.0f / 5.0f) * (az - zp * rowsum);
        float zn = zp + 0.005f * ((ag + rep) * (1.0f / 32.0f));
        out[OFF_ZNEW + p * 8192 + d] = zn;
    }
}

// ---------------- hard graphs ----------------
__global__ void s2_kernel(float* __restrict__ out) {
    int p = blockIdx.x >> 6, j = blockIdx.x & 63, i = threadIdx.x;
    __shared__ float vrow[64];
    __shared__ unsigned int mparts[2];
    const float* zn = out + OFF_ZNEW + p * 8192;
    vrow[i] = zn[(j * 64 + i) * 2 + 1];
    __syncthreads();
    double acc = 0.0;
    for (int k = 0; k < 64; k++) acc += (double)zn[(i * 64 + k) * 2] * (double)vrow[k];
    bool edge = (i != j && acc > 0.0);
    out[OFF_GHARD + p * 4096 + i * 64 + j] = edge ? 1.f : 0.f;
    unsigned bal = __ballot_sync(0xffffffffu, edge);
    if ((i & 31) == 0) mparts[i >> 5] = bal;
    __syncthreads();
    if (i == 0)
        g_colsh[p * 64 + j] = (unsigned long long)mparts[0]
                            | ((unsigned long long)mparts[1] << 32);
}

// ---------------- encoder L1 ----------------
__global__ void enc0_kernel(const float* __restrict__ out,
                            const float* __restrict__ ew0,
                            const float* __restrict__ eb0) {
    int gw = blockIdx.x * 8 + (threadIdx.x >> 5);
    if (gw >= 640) return;
    int p = gw / 20, o = gw % 20;
    int lane = threadIdx.x & 31;
    const float* gp = out + OFF_GHARD + p * 4096;
    float acc = 0.f;
    for (int t = lane; t < 4096; t += 32) acc = fmaf(gp[t], ew0[t * 20 + o], acc);
    for (int of = 16; of > 0; of >>= 1) acc += __shfl_xor_sync(0xffffffffu, acc, of);
    if (lane == 0) g_h0[p * 20 + o] = fmaxf(0.f, acc + eb0[o]);
}

// ---------------- remaining MLP layers: one block per particle ----------------
__global__ void __launch_bounds__(64) mlp_kernel(float* __restrict__ out,
    const float* ew1, const float* eb1, const float* ew2, const float* eb2,
    const float* mw0, const float* mb0, const float* mw1, const float* mb1,
    const float* lw0, const float* lb0, const float* lw1, const float* lb1,
    const float* dw0, const float* db0, const float* dw1, const float* db1,
    const float* dw2, const float* db2) {
    __shared__ float h0s[20];
    __shared__ float h1[64];
    __shared__ float h2[64];
    __shared__ float amu[64];
    __shared__ float qmu[64];
    __shared__ float alv[64];
    __shared__ float qz[64];
    __shared__ float hd0[10];
    __shared__ float hd1[128];
    int p = blockIdx.x, o = threadIdx.x;
    if (o < 20) h0s[o] = g_h0[p * 20 + o];
    __syncthreads();
    {
        float a = eb1[o];
        for (int t = 0; t < 20; t++) a = fmaf(h0s[t], ew1[t * 64 + o], a);
        h1[o] = fmaxf(0.f, a);
    }
    __syncthreads();
    {
        float a = eb2[o];
        for (int t = 0; t < 64; t++) a = fmaf(h1[t], ew2[t * 64 + o], a);
        h2[o] = fmaxf(0.f, a);
    }
    __syncthreads();
    {
        float a = mb0[o];
        for (int t = 0; t < 64; t++) a = fmaf(h2[t], mw0[t * 64 + o], a);
        amu[o] = fmaxf(0.f, a);
        float b = lb0[o];
        for (int t = 0; t < 64; t++) b = fmaf(h2[t], lw0[t * 64 + o], b);
        alv[o] = fmaxf(0.f, b);
    }
    __syncthreads();
    {
        float a = mb1[o];
        for (int t = 0; t < 64; t++) a = fmaf(amu[t], mw1[t * 64 + o], a);
        qmu[o] = a;
        out[OFF_QMU + p * 64 + o] = a;
        float b = lb1[o];
        for (int t = 0; t < 64; t++) b = fmaf(alv[t], lw1[t * 64 + o], b);
        out[OFF_QLV + p * 64 + o] = b;
        float eps = jax_normal(jax_bits32(g_keys[2], g_keys[3], (unsigned)(p * 64 + o)));
        float q = qmu[o] + eps * expf(0.5f * b);
        out[OFF_QZ + p * 64 + o] = q;
        qz[o] = q;
    }
    __syncthreads();
    if (o < 10) {
        float a = db0[o];
        for (int t = 0; t < 64; t++) a = fmaf(qz[t], dw0[t * 10 + o], a);
        hd0[o] = fmaxf(0.f, a);
    }
    __syncthreads();
#pragma unroll
    for (int g = 0; g < 2; g++) {
        int oo = o + g * 64;
        float a = db1[oo];
        for (int t = 0; t < 10; t++) a = fmaf(hd0[t], dw1[t * 128 + oo], a);
        hd1[oo] = fmaxf(0.f, a);
    }
    __syncthreads();
#pragma unroll
    for (int g = 0; g < 2; g++) {
        int oo = o + g * 64;
        float a = db2[oo];
        for (int t = 0; t < 128; t++) a = fmaf(hd1[t], dw2[t * 128 + oo], a);
        out[OFF_RECONS + p * 128 + oo] = a;
    }
}

// ---------------- launch ----------------
extern "C" void kernel_launch(void* const* d_in, const int* in_sizes, int n_in,
                              void* d_out, int out_size) {
    const float* z_gt = (const float*)d_in[0];
    const float* z0   = (const float*)d_in[1];
    const float* ew0 = (const float*)d_in[2];  const float* eb0 = (const float*)d_in[3];
    const float* ew1 = (const float*)d_in[4];  const float* eb1 = (const float*)d_in[5];
    const float* ew2 = (const float*)d_in[6];  const float* eb2 = (const float*)d_in[7];
    const float* mw0 = (const float*)d_in[8];  const float* mb0 = (const float*)d_in[9];
    const float* mw1 = (const float*)d_in[10]; const float* mb1 = (const float*)d_in[11];
    const float* lw0 = (const float*)d_in[12]; const float* lb0 = (const float*)d_in[13];
    const float* lw1 = (const float*)d_in[14]; const float* lb1 = (const float*)d_in[15];
    const float* dw0 = (const float*)d_in[16]; const float* db0 = (const float*)d_in[17];
    const float* dw1 = (const float*)d_in[18]; const float* db1 = (const float*)d_in[19];
    const float* dw2 = (const float*)d_in[20]; const float* db2 = (const float*)d_in[21];
    const int*   seed = (const int*)d_in[22];
    float* out = (float*)d_out;

    unsigned long long* colsMC; cudaGetSymbolAddress((void**)&colsMC, g_cols);
    unsigned long long* colsH;  cudaGetSymbolAddress((void**)&colsH,  g_colsh);
    double* nsMC;  cudaGetSymbolAddress((void**)&nsMC,  g_ns);
    double* nsH;   cudaGetSymbolAddress((void**)&nsH,   g_nsh);
    double* logpMC; cudaGetSymbolAddress((void**)&logpMC, g_logp);

    scores_kernel<<<Pn * 64, 64>>>(z0, z_gt, seed);            // 1: probs + xbar + init
    Rtile_kernel<<<16, 256>>>(z_gt);                           // 2: R partials
    bern_kernel<<<1024, 256>>>();                              // 3: sampling + R finalize
    bge_reg_kernel<<<NG * 64 / 8, 256>>>(colsMC, nsMC, NG * 64);   // 4 (profiled)
    bge_mid_kernel<<<NG * 64 / 8, 256>>>(colsMC, nsMC, NG * 64);
    bge_big_kernel<<<NG * 64 / 4, 128>>>(colsMC, nsMC, NG * 64);
    reduce64_kernel<<<NG, 64>>>(nsMC, logpMC);
    softmax_kernel<<<Pn, 32>>>();
    B_kernel<<<512, 256>>>();
    gradu_kernel<<<Pn * 64, 64>>>(z0);
    gradv_kernel<<<Pn * 64, 64>>>(z0);
    kmat_kernel<<<Pn, 1024>>>(z0);
    znew_kernel<<<Pn, 256>>>(z0, out);
    s2_kernel<<<Pn * 64, 64>>>(out);
    bge_reg_kernel<<<Pn * 64 / 8, 256>>>(colsH, nsH, Pn * 64);
    bge_mid_kernel<<<Pn * 64 / 8, 256>>>(colsH, nsH, Pn * 64);
    bge_big_kernel<<<Pn * 64 / 4, 128>>>(colsH, nsH, Pn * 64);
    reduce64h_kernel<<<Pn, 64>>>(nsH, out);
    enc0_kernel<<<80, 256>>>(out, ew0, eb0);
    mlp_kernel<<<Pn, 64>>>(out, ew1, eb1, ew2, eb2,
                           mw0, mb0, mw1, mb1, lw0, lb0, lw1, lb1,
                           dw0, db0, dw1, db1, dw2, db2);
}

// round 12
// speedup vs baseline: 1.0752x; 1.0752x over previous
#include <cuda_runtime.h>
#include <cuda_bf16.h>
#include <math.h>
#include <stdint.h>

// ---------------- problem constants ----------------
#define Dn    64
#define Pn    32
#define NMC   16
#define NG    512           // Pn*NMC
#define NOBS  2048
#define CAP   52            // max m handled by bge_small (l <= 51)
#define TRI_CAP 1378        // CAP*(CAP+1)/2
// output layout (floats)
#define OFF_RECONS 0
#define OFF_LOGP   4096
#define OFF_QZ     4128
#define OFF_QMU    6176
#define OFF_QLV    8224
#define OFF_GHARD  10272
#define OFF_ZNEW   141344

// ---------------- device scratch ----------------
static __device__ double             g_xbard[Dn];
static __device__ float              g_Rpart[16 * 4096];
static __device__ float              g_R[Dn * Dn];
static __device__ float              g_probs[Pn * Dn * Dn];
static __device__ unsigned long long g_cols[NG * Dn];
static __device__ unsigned long long g_colsh[Pn * Dn];
static __device__ double             g_ns[NG * Dn];
static __device__ double             g_nsh[Pn * Dn];
static __device__ double             g_w[NG];
static __device__ float              g_B[Pn * Dn * Dn];
static __device__ float              g_grads[Pn * Dn * Dn * 2];
static __device__ float              g_Kmat[Pn * Pn];
static __device__ unsigned int       g_keys[4];
static __device__ double             g_lgtab[64];
static __device__ double             g_logitpe;
static __device__ float              g_h0[Pn * 20];

// ---------------- threefry2x32 (JAX-exact) ----------------
__device__ __forceinline__ void tf2x32(unsigned k0, unsigned k1,
                                       unsigned x0, unsigned x1,
                                       unsigned &o0, unsigned &o1) {
    unsigned ks0 = k0, ks1 = k1, ks2 = k0 ^ k1 ^ 0x1BD11BDAu;
    x0 += ks0; x1 += ks1;
#define TFR(r) { x0 += x1; x1 = __funnelshift_l(x1, x1, r); x1 ^= x0; }
    TFR(13) TFR(15) TFR(26) TFR(6)   x0 += ks1; x1 += ks2 + 1u;
    TFR(17) TFR(29) TFR(16) TFR(24)  x0 += ks2; x1 += ks0 + 2u;
    TFR(13) TFR(15) TFR(26) TFR(6)   x0 += ks0; x1 += ks1 + 3u;
    TFR(17) TFR(29) TFR(16) TFR(24)  x0 += ks1; x1 += ks2 + 4u;
    TFR(13) TFR(15) TFR(26) TFR(6)   x0 += ks2; x1 += ks0 + 5u;
#undef TFR
    o0 = x0; o1 = x1;
}

__device__ __forceinline__ unsigned jax_bits32(unsigned k0, unsigned k1, unsigned idx) {
    unsigned o0, o1;
    tf2x32(k0, k1, 0u, idx, o0, o1);
    return o0 ^ o1;
}

__device__ __forceinline__ float u01f(unsigned b) {
    return __uint_as_float((b >> 9) | 0x3f800000u) - 1.0f;
}

__device__ __forceinline__ float jax_normal(unsigned bits) {
    const float lo = -0.99999994f;
    float f = u01f(bits);
    float u = fmaxf(lo, fmaf(f, 2.0f, lo));
    float w = -log1pf(-u * u);
    float p;
    if (w < 5.0f) {
        w -= 2.5f;
        p = 2.81022636e-08f;
        p = fmaf(p, w, 3.43273939e-07f);
        p = fmaf(p, w, -3.5233877e-06f);
        p = fmaf(p, w, -4.39150654e-06f);
        p = fmaf(p, w, 0.00021858087f);
        p = fmaf(p, w, -0.00125372503f);
        p = fmaf(p, w, -0.00417768164f);
        p = fmaf(p, w, 0.246640727f);
        p = fmaf(p, w, 1.50140941f);
    } else {
        w = sqrtf(w) - 3.0f;
        p = -0.000200214257f;
        p = fmaf(p, w, 0.000100950558f);
        p = fmaf(p, w, 0.00134934322f);
        p = fmaf(p, w, -0.00367342844f);
        p = fmaf(p, w, 0.00573950773f);
        p = fmaf(p, w, -0.0076224613f);
        p = fmaf(p, w, 0.00943887047f);
        p = fmaf(p, w, 1.00167406f);
        p = fmaf(p, w, 2.83297682f);
    }
    return 1.4142135381698608f * (p * u);
}

// ---------------- launch 1: scores ILPx4 (+init +xbar) ----------------
// block b: p = b>>4, ig = b&15; thread j; 4 dots (i = ig*4+r), each dot's
// f64 accumulation in the exact sequential k order (bit-identical probs).
__global__ void scores_kernel(const float* __restrict__ z,
                              const float* __restrict__ zgt,
                              const int* __restrict__ seed_ptr) {
    __shared__ double sx[64];
    int b = blockIdx.x;
    int p = b >> 4, ig = b & 15;
    int j = threadIdx.x;
    if (b < 64) {            // xbar duty: block b -> column b
        int col = b;
        double a = 0.0;
        int n0 = j * 32;
        for (int n = n0; n < n0 + 32; n++) a += (double)zgt[n * 64 + col];
        sx[j] = a;
        __syncthreads();
        for (int st = 32; st > 0; st >>= 1) {
            if (j < st) sx[j] += sx[j + st];
            __syncthreads();
        }
        if (j == 0) g_xbard[col] = sx[0] / 2048.0;
    }
    if (b == 0) {
        if (j == 0) {
            unsigned seed = (unsigned)seed_ptr[0];
            unsigned a0, a1, b0, b1;
            tf2x32(0u, seed, 0u, 0u, a0, a1);
            tf2x32(0u, seed, 0u, 1u, b0, b1);   // sk
            unsigned c0, c1, d0, d1;
            tf2x32(a0, a1, 0u, 0u, c0, c1);
            tf2x32(a0, a1, 0u, 1u, d0, d1);     // rk
            g_keys[0] = b0; g_keys[1] = b1;
            g_keys[2] = d0; g_keys[3] = d1;
            double pe = 4.0 / 63.0;
            g_logitpe = log(pe) - log1p(-pe);
        }
        const double LOG_PI   = 1.1447298858494001741;
        const double LOG_HALF = -0.6931471805599453094;
        double l = (double)j;
        g_lgtab[j] = -0.5 * log(2049.0)
                   + lgamma(0.5 * (2051.0 + l)) - lgamma(0.5 * (3.0 + l))
                   - 1024.0 * LOG_PI
                   + 0.5 * (3.0 + 2.0 * l) * LOG_HALF;
    }
    const float* zp = z + p * 8192;
    int i0 = ig * 4;
    double acc0 = 0.0, acc1 = 0.0, acc2 = 0.0, acc3 = 0.0;
    for (int k = 0; k < 64; k++) {
        double vj = (double)zp[(j * 64 + k) * 2 + 1];
        acc0 += (double)zp[((i0 + 0) * 64 + k) * 2] * vj;
        acc1 += (double)zp[((i0 + 1) * 64 + k) * 2] * vj;
        acc2 += (double)zp[((i0 + 2) * 64 + k) * 2] * vj;
        acc3 += (double)zp[((i0 + 3) * 64 + k) * 2] * vj;
    }
    double accs[4] = {acc0, acc1, acc2, acc3};
#pragma unroll
    for (int r = 0; r < 4; r++) {
        int i = i0 + r;
        float sc = (float)accs[r];
        float tl = 0.2f * sc;
        float pr = (i == j) ? 0.f : (0.5f * tanhf(0.5f * tl) + 0.5f);  // XLA logistic
        g_probs[p * 4096 + i * 64 + j] = pr;
    }
}

// ---------------- launch 2: R tile partials (16 blocks x 256) ----------------
__global__ void Rtile_kernel(const float* __restrict__ zgt) {
    __shared__ float xs[128 * 64];
    int tid = threadIdx.x;
    int nb = blockIdx.x * 128;
    for (int idx = tid; idx < 128 * 64; idx += 256) {
        int n = idx >> 6, c = idx & 63;
        xs[idx] = zgt[(nb + n) * 64 + c] - (float)g_xbard[c];
    }
    __syncthreads();
    int i0 = (tid >> 4) << 2, j0 = (tid & 15) << 2;
    float acc[4][4];
#pragma unroll
    for (int r = 0; r < 4; r++)
#pragma unroll
        for (int c = 0; c < 4; c++) acc[r][c] = 0.f;
    for (int n = 0; n < 128; n++) {
        float4 a = *reinterpret_cast<const float4*>(&xs[n * 64 + i0]);
        float4 b = *reinterpret_cast<const float4*>(&xs[n * 64 + j0]);
        float ar[4] = {a.x, a.y, a.z, a.w};
        float br[4] = {b.x, b.y, b.z, b.w};
#pragma unroll
        for (int r = 0; r < 4; r++)
#pragma unroll
            for (int c = 0; c < 4; c++) acc[r][c] = fmaf(ar[r], br[c], acc[r][c]);
    }
    float* out = g_Rpart + blockIdx.x * 4096;
#pragma unroll
    for (int r = 0; r < 4; r++)
#pragma unroll
        for (int c = 0; c < 4; c++) out[(i0 + r) * 64 + (j0 + c)] = acc[r][c];
}

// ---------------- launch 3: bernoulli (+R finalize in blocks 0..15) ----------------
__global__ void __launch_bounds__(256) bern_kernel() {
    if (blockIdx.x < 16) {
        int idx = blockIdx.x * 256 + threadIdx.x;   // 0..4095
        int i = idx >> 6, jj = idx & 63;
        double s = 0.0;
        for (int b = 0; b < 16; b++) s += (double)g_Rpart[b * 4096 + idx];
        s += (2048.0 / 2049.0) * g_xbard[i] * g_xbard[jj];
        if (i == jj) s += 0.5;
        g_R[idx] = (float)s;
    }
    int gid = blockIdx.x * 256 + threadIdx.x;   // 262144 = 32768 cols * 8
    int part = gid & 7;
    int col = gid >> 3;                         // (p*16+s)*64 + j
    int j = col & 63, p = col >> 10;
    unsigned k0 = g_keys[0], k1 = g_keys[1];
    const float* pr = g_probs + p * 4096;
    int i0 = part * 8;
    unsigned base = (unsigned)((col >> 6) * 4096 + i0 * 64 + j);
    unsigned long long m = 0ull;
#pragma unroll
    for (int r = 0; r < 8; r++) {
        unsigned bits = jax_bits32(k0, k1, base + (unsigned)(r * 64));
        if (u01f(bits) < pr[(i0 + r) * 64 + j]) m |= 1ull << (i0 + r);
    }
    m |= __shfl_xor_sync(0xffffffffu, m, 1);
    m |= __shfl_xor_sync(0xffffffffu, m, 2);
    m |= __shfl_xor_sync(0xffffffffu, m, 4);
    if (part == 0) g_cols[col] = m;
}

// ---------------- launch 4 (profiled): BGe small (m <= CAP), R10-proven ----------------
// score_j = lg(l) - 0.5*logdet(R[S,S]) - 0.5*(2051+l)*log(schur pivot of j)
__global__ void __launch_bounds__(256) bge_small_kernel(
        const unsigned long long* __restrict__ cols,
        double* __restrict__ ns, int ntask) {
    __shared__ float sT[8][TRI_CAP];
    __shared__ unsigned char sidx[8][64];
    int w = threadIdx.x >> 5, lane = threadIdx.x & 31;
    int task = blockIdx.x * 8 + w;
    if (task >= ntask) return;
    unsigned long long mask = cols[task];
    int l = __popcll(mask);
    int m = l + 1;
    if (m > CAP) return;                 // rare: bge_big handles
    int j = task & 63;
    unsigned char* idx = sidx[w];
    if (lane == 0) {
        unsigned long long mm = mask; int c = 0;
        while (mm) { int b = __ffsll(mm) - 1; idx[c++] = (unsigned char)b; mm &= mm - 1; }
        idx[l] = (unsigned char)j;
    }
    __syncwarp();
    float* T = sT[w];
    {
        int base = 0;
        for (int a = 0; a < m; a++) {
            const float* Rrow = g_R + (int)idx[a] * 64;
            for (int b = a + lane; b < m; b += 32) T[base + b - a] = Rrow[idx[b]];
            base += m - a;
        }
    }
    __syncwarp();
    float logA = 0.f, lastpiv = 1.f;
    int basek = 0;
    int k = 0;
    if (m <= 33) {
        // single-column rank-2 path
        while (k + 1 < m) {
            int basek1 = basek + (m - k);
            float pivk = T[basek];
            float inv = 1.0f / pivk;
            float akk1 = T[basek + 1];
            int ja0 = k + 1 + lane;
            if (ja0 < m) {
                float t = T[basek + ja0 - k] * inv;
                T[basek1 + ja0 - (k + 1)] -= akk1 * t;
            }
            __syncwarp();
            float pivk1 = T[basek1];
            float inv2 = 1.0f / pivk1;
            if (lane == 0) {
                logA += logf(pivk);
                if (k + 1 < m - 1) logA += logf(pivk1);
                else lastpiv = pivk1;
            }
            int jb0 = k + 2 + lane;
            float t0 = 0.f, s0 = 0.f;
            if (jb0 < m) {
                t0 = T[basek + jb0 - k] * inv;
                s0 = T[basek1 + jb0 - k - 1] * inv2;
            }
            int bi = basek1 + (m - k - 1);
            for (int i = k + 2; i < m; i++) {
                float aki = T[basek + i - k];
                float bki = T[basek1 + i - k - 1];
                if (jb0 >= i && jb0 < m) {
                    float x = T[bi + jb0 - i];
                    x -= aki * t0;
                    x -= bki * s0;
                    T[bi + jb0 - i] = x;
                }
                bi += m - i;
            }
            basek = basek1 + (m - k - 1);
            k += 2;
            __syncwarp();
        }
    } else {
        // dual-column rank-2 path (m in 34..52)
        while (k + 1 < m) {
            int basek1 = basek + (m - k);
            float pivk = T[basek];
            float inv = 1.0f / pivk;
            float akk1 = T[basek + 1];
            int ja0 = k + 1 + lane, ja1 = ja0 + 32;
            if (ja0 < m) {
                float t = T[basek + ja0 - k] * inv;
                T[basek1 + ja0 - (k + 1)] -= akk1 * t;
            }
            if (ja1 < m) {
                float t = T[basek + ja1 - k] * inv;
                T[basek1 + ja1 - (k + 1)] -= akk1 * t;
            }
            __syncwarp();
            float pivk1 = T[basek1];
            float inv2 = 1.0f / pivk1;
            if (lane == 0) {
                logA += logf(pivk);
                if (k + 1 < m - 1) logA += logf(pivk1);
                else lastpiv = pivk1;
            }
            int jb0 = k + 2 + lane, jb1 = jb0 + 32;
            float t0 = 0.f, s0 = 0.f, t1 = 0.f, s1 = 0.f;
            if (jb0 < m) {
                t0 = T[basek + jb0 - k] * inv;
                s0 = T[basek1 + jb0 - k - 1] * inv2;
            }
            if (jb1 < m) {
                t1 = T[basek + jb1 - k] * inv;
                s1 = T[basek1 + jb1 - k - 1] * inv2;
            }
            int bi = basek1 + (m - k - 1);
            for (int i = k + 2; i < m; i++) {
                float aki = T[basek + i - k];
                float bki = T[basek1 + i - k - 1];
                if (jb0 >= i && jb0 < m) {
                    float x = T[bi + jb0 - i];
                    x -= aki * t0;
                    x -= bki * s0;
                    T[bi + jb0 - i] = x;
                }
                if (jb1 >= i && jb1 < m) {
                    float x = T[bi + jb1 - i];
                    x -= aki * t1;
                    x -= bki * s1;
                    T[bi + jb1 - i] = x;
                }
                bi += m - i;
            }
            basek = basek1 + (m - k - 1);
            k += 2;
            __syncwarp();
        }
    }
    if (k < m) lastpiv = T[basek];       // odd m: last pivot untouched by pairs
    if (lane == 0) {
        ns[task] = g_lgtab[l] - 0.5 * (double)logA
                 - 0.5 * (2051.0 + (double)l) * log((double)lastpiv);
    }
}

// ---------------- fallback: BGe big (m > CAP only) ----------------
__global__ void __launch_bounds__(128) bge_big_kernel(
        const unsigned long long* __restrict__ cols,
        double* __restrict__ ns, int ntask) {
    __shared__ float sT[4][2080];
    __shared__ unsigned char sidx[4][64];
    int w = threadIdx.x >> 5, lane = threadIdx.x & 31;
    int task = blockIdx.x * 4 + w;
    if (task >= ntask) return;
    unsigned long long mask = cols[task];
    int l = __popcll(mask);
    int m = l + 1;
    if (m <= CAP) return;
    int j = task & 63;
    unsigned char* idx = sidx[w];
    if (lane == 0) {
        unsigned long long mm = mask; int c = 0;
        while (mm) { int b = __ffsll(mm) - 1; idx[c++] = (unsigned char)b; mm &= mm - 1; }
        idx[l] = (unsigned char)j;
    }
    __syncwarp();
    float* T = sT[w];
    {
        int base = 0;
        for (int a = 0; a < m; a++) {
            const float* Rrow = g_R + (int)idx[a] * 64;
            for (int b = a + lane; b < m; b += 32) T[base + b - a] = Rrow[idx[b]];
            base += m - a;
        }
    }
    __syncwarp();
    float logA = 0.f, lastpiv = 1.f;
    int basek = 0;
    int k = 0;
    for (; k < m - 33; k++) {
        float piv = T[basek];
        if (lane == 0) logA += logf(piv);
        float inv = 1.0f / piv;
        int j0 = k + 1 + lane, j1 = j0 + 32;
        float t0 = T[basek + 1 + lane] * inv;
        float t1 = (j1 < m) ? T[basek + 33 + lane] * inv : 0.f;
        int bi = basek + (m - k);
        for (int i = k + 1; i < m; i++) {
            float aki = T[basek + i - k];
            if (j0 >= i)           T[bi + j0 - i] -= aki * t0;
            if (j1 >= i && j1 < m) T[bi + j1 - i] -= aki * t1;
            bi += m - i;
        }
        basek += m - k;
        __syncwarp();
    }
    for (; k < m; k++) {
        float piv = T[basek];
        if (lane == 0) {
            if (k < m - 1) logA += logf(piv);
            else lastpiv = piv;
        }
        int rem = m - 1 - k;
        if (rem > 0) {
            float inv = 1.0f / piv;
            int j0 = k + 1 + lane;
            float t0 = (lane < rem) ? T[basek + 1 + lane] * inv : 0.f;
            int bi = basek + (m - k);
            for (int i = k + 1; i < m; i++) {
                float aki = T[basek + i - k];
                if (j0 >= i && j0 < m) T[bi + j0 - i] -= aki * t0;
                bi += m - i;
            }
        }
        basek += m - k;
        __syncwarp();
    }
    if (lane == 0) {
        ns[task] = g_lgtab[l] - 0.5 * (double)logA
                 - 0.5 * (2051.0 + (double)l) * log((double)lastpiv);
    }
}

// ---------------- fused reduce + softmax (MC): block per particle ----------------
// logp_MC only feeds softmax; reduction order free (continuous path).
__global__ void __launch_bounds__(512) redsoft_kernel() {
    __shared__ double sv[16];
    int p = blockIdx.x;
    int s = threadIdx.x >> 5, lane = threadIdx.x & 31;
    const double* nsg = g_ns + (p * 16 + s) * 64;
    double a = nsg[lane] + nsg[lane + 32];
    for (int o = 16; o > 0; o >>= 1) a += __shfl_xor_sync(0xffffffffu, a, o);
    if (lane == 0) sv[s] = a;
    __syncthreads();
    if (threadIdx.x < 32) {
        double v = (lane < 16) ? sv[lane] : -1e300;
        double mx = v;
        for (int o = 16; o > 0; o >>= 1) mx = fmax(mx, __shfl_xor_sync(0xffffffffu, mx, o));
        double e = (lane < 16) ? exp(v - mx) : 0.0;
        double sm = e;
        for (int o = 16; o > 0; o >>= 1) sm += __shfl_xor_sync(0xffffffffu, sm, o);
        if (lane < 16) g_w[p * 16 + lane] = e / sm;
    }
}

// hard graphs: deterministic tree reduce straight into the float output slot
__global__ void reduce64h_kernel(const double* __restrict__ ns, float* __restrict__ out) {
    __shared__ double s[64];
    int g = blockIdx.x, t = threadIdx.x;
    s[t] = ns[g * 64 + t];
    __syncthreads();
    for (int st = 32; st > 0; st >>= 1) {
        if (t < st) s[t] += s[t + st];
        __syncthreads();
    }
    if (t == 0) out[OFF_LOGP + g] = (float)s[0];
}

// ---------------- B ----------------
__global__ void B_kernel() {
    int idx = blockIdx.x * blockDim.x + threadIdx.x;
    int j = idx & 63, i = (idx >> 6) & 63, p = idx >> 12;
    float pr = g_probs[p * 4096 + i * 64 + j];
    double ws = 0.0;
    for (int s = 0; s < 16; s++)
        if ((g_cols[(p * 16 + s) * 64 + j] >> i) & 1ull) ws += g_w[p * 16 + s];
    float B = 0.f;
    if (i != j)
        B = 0.2f * ((float)ws - pr) + 0.2f * pr * (1.f - pr) * (float)g_logitpe;
    g_B[idx] = B;
}

// ---------------- grads (fused u/v) ----------------
__global__ void gradufv_kernel(const float* __restrict__ z) {
    int bb = blockIdx.x;
    int k = threadIdx.x;
    if (bb < 2048) {
        int p = bb >> 6, i = bb & 63;
        const float* Bp = g_B + p * 4096 + i * 64;
        const float* zp = z + p * 8192;
        float acc = 0.f;
        for (int j = 0; j < 64; j++) acc = fmaf(Bp[j], zp[(j * 64 + k) * 2 + 1], acc);
        float u = zp[(i * 64 + k) * 2];
        g_grads[(bb * 64 + k) * 2] = acc - 64.f * u;
    } else {
        int b2 = bb - 2048;
        int p = b2 >> 6, j = b2 & 63;
        const float* Bp = g_B + p * 4096;
        const float* zp = z + p * 8192;
        float acc = 0.f;
        for (int i = 0; i < 64; i++) acc = fmaf(Bp[i * 64 + j], zp[(i * 64 + k) * 2], acc);
        float v = zp[(j * 64 + k) * 2 + 1];
        g_grads[((p * 64 + j) * 64 + k) * 2 + 1] = acc - 64.f * v;
    }
}

// ---------------- SVGD ----------------
__global__ void kmat_kernel(const float* __restrict__ z) {
    int p = blockIdx.x;
    int q = threadIdx.x >> 5, lane = threadIdx.x & 31;
    const float* a = z + p * 8192;
    const float* b = z + q * 8192;
    double sq = 0.0;
    for (int t = lane; t < 8192; t += 32) {
        double d = (double)a[t] - (double)b[t];
        sq += d * d;
    }
    for (int o = 16; o > 0; o >>= 1) sq += __shfl_xor_sync(0xffffffffu, sq, o);
    if (lane == 0) g_Kmat[p * 32 + q] = (float)exp(-sq / 5.0);
}

__global__ void znew_kernel(const float* __restrict__ z, float* __restrict__ out) {
    int p = blockIdx.x;
    __shared__ float kr[32];
    __shared__ float rowsum;
    if (threadIdx.x < 32) kr[threadIdx.x] = g_Kmat[p * 32 + threadIdx.x];
    __syncthreads();
    if (threadIdx.x == 0) {
        float s = 0.f;
        for (int q = 0; q < 32; q++) s += kr[q];
        rowsum = s;
    }
    __syncthreads();
    for (int d = threadIdx.x; d < 8192; d += blockDim.x) {
        float ag = 0.f, az = 0.f;
        for (int q = 0; q < 32; q++) {
            float kk = kr[q];
            ag = fmaf(kk, g_grads[q * 8192 + d], ag);
            az = fmaf(kk, z[q * 8192 + d], az);
        }
        float zp = z[p * 8192 + d];
        float rep = (-2.0f / 5.0f) * (az - zp * rowsum);
        float zn = zp + 0.005f * ((ag + rep) * (1.0f / 32.0f));
        out[OFF_ZNEW + p * 8192 + d] = zn;
    }
}

// ---------------- hard graphs: ILPx4 (thread=i, 4 j's), ballot masks ----------------
// Per-dot f64 accumulation in the exact sequential k order (bit-identical signs).
__global__ void s2_kernel(float* __restrict__ out) {
    __shared__ unsigned int mparts[2][4];
    int b = blockIdx.x;
    int p = b >> 4, jg = b & 15;
    int i = threadIdx.x;                 // 0..63, two warps
    const float* zn = out + OFF_ZNEW + p * 8192;
    int j0 = jg * 4;
    double acc0 = 0.0, acc1 = 0.0, acc2 = 0.0, acc3 = 0.0;
    for (int k = 0; k < 64; k++) {
        double ui = (double)zn[(i * 64 + k) * 2];
        acc0 += ui * (double)zn[((j0 + 0) * 64 + k) * 2 + 1];
        acc1 += ui * (double)zn[((j0 + 1) * 64 + k) * 2 + 1];
        acc2 += ui * (double)zn[((j0 + 2) * 64 + k) * 2 + 1];
        acc3 += ui * (double)zn[((j0 + 3) * 64 + k) * 2 + 1];
    }
    double accs[4] = {acc0, acc1, acc2, acc3};
#pragma unroll
    for (int r = 0; r < 4; r++) {
        int j = j0 + r;
        bool edge = (i != j && accs[r] > 0.0);
        out[OFF_GHARD + p * 4096 + i * 64 + j] = edge ? 1.f : 0.f;
        unsigned bal = __ballot_sync(0xffffffffu, edge);
        if ((i & 31) == 0) mparts[i >> 5][r] = bal;
    }
    __syncthreads();
    if (i < 4)
        g_colsh[p * 64 + j0 + i] = (unsigned long long)mparts[0][i]
                                 | ((unsigned long long)mparts[1][i] << 32);
}

// ---------------- encoder L1 ----------------
__global__ void enc0_kernel(const float* __restrict__ out,
                            const float* __restrict__ ew0,
                            const float* __restrict__ eb0) {
    int gw = blockIdx.x * 8 + (threadIdx.x >> 5);
    if (gw >= 640) return;
    int p = gw / 20, o = gw % 20;
    int lane = threadIdx.x & 31;
    const float* gp = out + OFF_GHARD + p * 4096;
    float acc = 0.f;
    for (int t = lane; t < 4096; t += 32) acc = fmaf(gp[t], ew0[t * 20 + o], acc);
    for (int of = 16; of > 0; of >>= 1) acc += __shfl_xor_sync(0xffffffffu, acc, of);
    if (lane == 0) g_h0[p * 20 + o] = fmaxf(0.f, acc + eb0[o]);
}

// ---------------- remaining MLP layers: one block per particle ----------------
__global__ void __launch_bounds__(64) mlp_kernel(float* __restrict__ out,
    const float* ew1, const float* eb1, const float* ew2, const float* eb2,
    const float* mw0, const float* mb0, const float* mw1, const float* mb1,
    const float* lw0, const float* lb0, const float* lw1, const float* lb1,
    const float* dw0, const float* db0, const float* dw1, const float* db1,
    const float* dw2, const float* db2) {
    __shared__ float h0s[20];
    __shared__ float h1[64];
    __shared__ float h2[64];
    __shared__ float amu[64];
    __shared__ float qmu[64];
    __shared__ float alv[64];
    __shared__ float qz[64];
    __shared__ float hd0[10];
    __shared__ float hd1[128];
    int p = blockIdx.x, o = threadIdx.x;
    if (o < 20) h0s[o] = g_h0[p * 20 + o];
    __syncthreads();
    {
        float a = eb1[o];
        for (int t = 0; t < 20; t++) a = fmaf(h0s[t], ew1[t * 64 + o], a);
        h1[o] = fmaxf(0.f, a);
    }
    __syncthreads();
    {
        float a = eb2[o];
        for (int t = 0; t < 64; t++) a = fmaf(h1[t], ew2[t * 64 + o], a);
        h2[o] = fmaxf(0.f, a);
    }
    __syncthreads();
    {
        float a = mb0[o];
        for (int t = 0; t < 64; t++) a = fmaf(h2[t], mw0[t * 64 + o], a);
        amu[o] = fmaxf(0.f, a);
        float b = lb0[o];
        for (int t = 0; t < 64; t++) b = fmaf(h2[t], lw0[t * 64 + o], b);
        alv[o] = fmaxf(0.f, b);
    }
    __syncthreads();
    {
        float a = mb1[o];
        for (int t = 0; t < 64; t++) a = fmaf(amu[t], mw1[t * 64 + o], a);
        qmu[o] = a;
        out[OFF_QMU + p * 64 + o] = a;
        float b = lb1[o];
        for (int t = 0; t < 64; t++) b = fmaf(alv[t], lw1[t * 64 + o], b);
        out[OFF_QLV + p * 64 + o] = b;
        float eps = jax_normal(jax_bits32(g_keys[2], g_keys[3], (unsigned)(p * 64 + o)));
        float q = qmu[o] + eps * expf(0.5f * b);
        out[OFF_QZ + p * 64 + o] = q;
        qz[o] = q;
    }
    __syncthreads();
    if (o < 10) {
        float a = db0[o];
        for (int t = 0; t < 64; t++) a = fmaf(qz[t], dw0[t * 10 + o], a);
        hd0[o] = fmaxf(0.f, a);
    }
    __syncthreads();
#pragma unroll
    for (int g = 0; g < 2; g++) {
        int oo = o + g * 64;
        float a = db1[oo];
        for (int t = 0; t < 10; t++) a = fmaf(hd0[t], dw1[t * 128 + oo], a);
        hd1[oo] = fmaxf(0.f, a);
    }
    __syncthreads();
#pragma unroll
    for (int g = 0; g < 2; g++) {
        int oo = o + g * 64;
        float a = db2[oo];
        for (int t = 0; t < 128; t++) a = fmaf(hd1[t], dw2[t * 128 + oo], a);
        out[OFF_RECONS + p * 128 + oo] = a;
    }
}

// ---------------- launch ----------------
extern "C" void kernel_launch(void* const* d_in, const int* in_sizes, int n_in,
                              void* d_out, int out_size) {
    const float* z_gt = (const float*)d_in[0];
    const float* z0   = (const float*)d_in[1];
    const float* ew0 = (const float*)d_in[2];  const float* eb0 = (const float*)d_in[3];
    const float* ew1 = (const float*)d_in[4];  const float* eb1 = (const float*)d_in[5];
    const float* ew2 = (const float*)d_in[6];  const float* eb2 = (const float*)d_in[7];
    const float* mw0 = (const float*)d_in[8];  const float* mb0 = (const float*)d_in[9];
    const float* mw1 = (const float*)d_in[10]; const float* mb1 = (const float*)d_in[11];
    const float* lw0 = (const float*)d_in[12]; const float* lb0 = (const float*)d_in[13];
    const float* lw1 = (const float*)d_in[14]; const float* lb1 = (const float*)d_in[15];
    const float* dw0 = (const float*)d_in[16]; const float* db0 = (const float*)d_in[17];
    const float* dw1 = (const float*)d_in[18]; const float* db1 = (const float*)d_in[19];
    const float* dw2 = (const float*)d_in[20]; const float* db2 = (const float*)d_in[21];
    const int*   seed = (const int*)d_in[22];
    float* out = (float*)d_out;

    unsigned long long* colsMC; cudaGetSymbolAddress((void**)&colsMC, g_cols);
    unsigned long long* colsH;  cudaGetSymbolAddress((void**)&colsH,  g_colsh);
    double* nsMC;  cudaGetSymbolAddress((void**)&nsMC,  g_ns);
    double* nsH;   cudaGetSymbolAddress((void**)&nsH,   g_nsh);

    scores_kernel<<<512, 64>>>(z0, z_gt, seed);                // 1: probs + xbar + init
    Rtile_kernel<<<16, 256>>>(z_gt);                           // 2: R partials
    bern_kernel<<<1024, 256>>>();                              // 3: sampling + R finalize
    bge_small_kernel<<<NG * 64 / 8, 256>>>(colsMC, nsMC, NG * 64);  // 4 (profiled)
    bge_big_kernel<<<NG * 64 / 4, 128>>>(colsMC, nsMC, NG * 64);
    redsoft_kernel<<<Pn, 512>>>();
    B_kernel<<<512, 256>>>();
    gradufv_kernel<<<4096, 64>>>(z0);
    kmat_kernel<<<Pn, 1024>>>(z0);
    znew_kernel<<<Pn, 256>>>(z0, out);
    s2_kernel<<<512, 64>>>(out);
    bge_small_kernel<<<Pn * 64 / 8, 256>>>(colsH, nsH, Pn * 64);
    bge_big_kernel<<<Pn * 64 / 4, 128>>>(colsH, nsH, Pn * 64);
    reduce64h_kernel<<<Pn, 64>>>(nsH, out);
    enc0_kernel<<<80, 256>>>(out, ew0, eb0);
    mlp_kernel<<<Pn, 64>>>(out, ew1, eb1, ew2, eb2,
                           mw0, mb0, mw1, mb1, lw0, lb0, lw1, lb1,
                           dw0, db0, dw1, db1, dw2, db2);
}

// round 13
// speedup vs baseline: 1.5787x; 1.4683x over previous
#include <cuda_runtime.h>
#include <cuda_bf16.h>
#include <math.h>
#include <stdint.h>

// ---------------- problem constants ----------------
#define Dn    64
#define Pn    32
#define NMC   16
#define NG    512           // Pn*NMC
#define NOBS  2048
#define CAP   52            // max m handled by bge_small (l <= 51)
#define TRI_CAP 1378        // CAP*(CAP+1)/2
// output layout (floats)
#define OFF_RECONS 0
#define OFF_LOGP   4096
#define OFF_QZ     4128
#define OFF_QMU    6176
#define OFF_QLV    8224
#define OFF_GHARD  10272
#define OFF_ZNEW   141344

// ---------------- device scratch ----------------
static __device__ double             g_xbard[Dn];
static __device__ float              g_Rpart[16 * 4096];
static __device__ float              g_R[Dn * Dn];
static __device__ float              g_probs[Pn * Dn * Dn];
static __device__ unsigned long long g_cols[NG * Dn];
static __device__ unsigned long long g_colsh[Pn * Dn];
static __device__ double             g_ns[NG * Dn];
static __device__ double             g_nsh[Pn * Dn];
static __device__ double             g_w[NG];
static __device__ float              g_B[Pn * Dn * Dn];
static __device__ float              g_grads[Pn * Dn * Dn * 2];
static __device__ float              g_Kmat[Pn * Pn];
static __device__ unsigned int       g_keys[4];
static __device__ double             g_lgtab[64];
static __device__ double             g_logitpe;
static __device__ float              g_h0[Pn * 20];

// ---------------- threefry2x32 (JAX-exact) ----------------
__device__ __forceinline__ void tf2x32(unsigned k0, unsigned k1,
                                       unsigned x0, unsigned x1,
                                       unsigned &o0, unsigned &o1) {
    unsigned ks0 = k0, ks1 = k1, ks2 = k0 ^ k1 ^ 0x1BD11BDAu;
    x0 += ks0; x1 += ks1;
#define TFR(r) { x0 += x1; x1 = __funnelshift_l(x1, x1, r); x1 ^= x0; }
    TFR(13) TFR(15) TFR(26) TFR(6)   x0 += ks1; x1 += ks2 + 1u;
    TFR(17) TFR(29) TFR(16) TFR(24)  x0 += ks2; x1 += ks0 + 2u;
    TFR(13) TFR(15) TFR(26) TFR(6)   x0 += ks0; x1 += ks1 + 3u;
    TFR(17) TFR(29) TFR(16) TFR(24)  x0 += ks1; x1 += ks2 + 4u;
    TFR(13) TFR(15) TFR(26) TFR(6)   x0 += ks2; x1 += ks0 + 5u;
#undef TFR
    o0 = x0; o1 = x1;
}

__device__ __forceinline__ unsigned jax_bits32(unsigned k0, unsigned k1, unsigned idx) {
    unsigned o0, o1;
    tf2x32(k0, k1, 0u, idx, o0, o1);
    return o0 ^ o1;
}

__device__ __forceinline__ float u01f(unsigned b) {
    return __uint_as_float((b >> 9) | 0x3f800000u) - 1.0f;
}

__device__ __forceinline__ float jax_normal(unsigned bits) {
    const float lo = -0.99999994f;
    float f = u01f(bits);
    float u = fmaxf(lo, fmaf(f, 2.0f, lo));
    float w = -log1pf(-u * u);
    float p;
    if (w < 5.0f) {
        w -= 2.5f;
        p = 2.81022636e-08f;
        p = fmaf(p, w, 3.43273939e-07f);
        p = fmaf(p, w, -3.5233877e-06f);
        p = fmaf(p, w, -4.39150654e-06f);
        p = fmaf(p, w, 0.00021858087f);
        p = fmaf(p, w, -0.00125372503f);
        p = fmaf(p, w, -0.00417768164f);
        p = fmaf(p, w, 0.246640727f);
        p = fmaf(p, w, 1.50140941f);
    } else {
        w = sqrtf(w) - 3.0f;
        p = -0.000200214257f;
        p = fmaf(p, w, 0.000100950558f);
        p = fmaf(p, w, 0.00134934322f);
        p = fmaf(p, w, -0.00367342844f);
        p = fmaf(p, w, 0.00573950773f);
        p = fmaf(p, w, -0.0076224613f);
        p = fmaf(p, w, 0.00943887047f);
        p = fmaf(p, w, 1.00167406f);
        p = fmaf(p, w, 2.83297682f);
    }
    return 1.4142135381698608f * (p * u);
}

// ---------------- launch 1: scores ILPx4 (+init +xbar) ----------------
__global__ void scores_kernel(const float* __restrict__ z,
                              const float* __restrict__ zgt,
                              const int* __restrict__ seed_ptr) {
    __shared__ double sx[64];
    int b = blockIdx.x;
    int p = b >> 4, ig = b & 15;
    int j = threadIdx.x;
    if (b < 64) {            // xbar duty: block b -> column b
        int col = b;
        double a = 0.0;
        int n0 = j * 32;
        for (int n = n0; n < n0 + 32; n++) a += (double)zgt[n * 64 + col];
        sx[j] = a;
        __syncthreads();
        for (int st = 32; st > 0; st >>= 1) {
            if (j < st) sx[j] += sx[j + st];
            __syncthreads();
        }
        if (j == 0) g_xbard[col] = sx[0] / 2048.0;
    }
    if (b == 0) {
        if (j == 0) {
            unsigned seed = (unsigned)seed_ptr[0];
            unsigned a0, a1, b0, b1;
            tf2x32(0u, seed, 0u, 0u, a0, a1);
            tf2x32(0u, seed, 0u, 1u, b0, b1);   // sk
            unsigned c0, c1, d0, d1;
            tf2x32(a0, a1, 0u, 0u, c0, c1);
            tf2x32(a0, a1, 0u, 1u, d0, d1);     // rk
            g_keys[0] = b0; g_keys[1] = b1;
            g_keys[2] = d0; g_keys[3] = d1;
            double pe = 4.0 / 63.0;
            g_logitpe = log(pe) - log1p(-pe);
        }
        const double LOG_PI   = 1.1447298858494001741;
        const double LOG_HALF = -0.6931471805599453094;
        double l = (double)j;
        g_lgtab[j] = -0.5 * log(2049.0)
                   + lgamma(0.5 * (2051.0 + l)) - lgamma(0.5 * (3.0 + l))
                   - 1024.0 * LOG_PI
                   + 0.5 * (3.0 + 2.0 * l) * LOG_HALF;
    }
    const float* zp = z + p * 8192;
    int i0 = ig * 4;
    double acc0 = 0.0, acc1 = 0.0, acc2 = 0.0, acc3 = 0.0;
    for (int k = 0; k < 64; k++) {
        double vj = (double)zp[(j * 64 + k) * 2 + 1];
        acc0 += (double)zp[((i0 + 0) * 64 + k) * 2] * vj;
        acc1 += (double)zp[((i0 + 1) * 64 + k) * 2] * vj;
        acc2 += (double)zp[((i0 + 2) * 64 + k) * 2] * vj;
        acc3 += (double)zp[((i0 + 3) * 64 + k) * 2] * vj;
    }
    double accs[4] = {acc0, acc1, acc2, acc3};
#pragma unroll
    for (int r = 0; r < 4; r++) {
        int i = i0 + r;
        float sc = (float)accs[r];
        float tl = 0.2f * sc;
        float pr = (i == j) ? 0.f : (0.5f * tanhf(0.5f * tl) + 0.5f);  // XLA logistic
        g_probs[p * 4096 + i * 64 + j] = pr;
    }
}

// ---------------- launch 2: R tile partials (16 blocks x 256) ----------------
__global__ void Rtile_kernel(const float* __restrict__ zgt) {
    __shared__ float xs[128 * 64];
    int tid = threadIdx.x;
    int nb = blockIdx.x * 128;
    for (int idx = tid; idx < 128 * 64; idx += 256) {
        int n = idx >> 6, c = idx & 63;
        xs[idx] = zgt[(nb + n) * 64 + c] - (float)g_xbard[c];
    }
    __syncthreads();
    int i0 = (tid >> 4) << 2, j0 = (tid & 15) << 2;
    float acc[4][4];
#pragma unroll
    for (int r = 0; r < 4; r++)
#pragma unroll
        for (int c = 0; c < 4; c++) acc[r][c] = 0.f;
    for (int n = 0; n < 128; n++) {
        float4 a = *reinterpret_cast<const float4*>(&xs[n * 64 + i0]);
        float4 b = *reinterpret_cast<const float4*>(&xs[n * 64 + j0]);
        float ar[4] = {a.x, a.y, a.z, a.w};
        float br[4] = {b.x, b.y, b.z, b.w};
#pragma unroll
        for (int r = 0; r < 4; r++)
#pragma unroll
            for (int c = 0; c < 4; c++) acc[r][c] = fmaf(ar[r], br[c], acc[r][c]);
    }
    float* out = g_Rpart + blockIdx.x * 4096;
#pragma unroll
    for (int r = 0; r < 4; r++)
#pragma unroll
        for (int c = 0; c < 4; c++) out[(i0 + r) * 64 + (j0 + c)] = acc[r][c];
}

// ---------------- launch 3: bernoulli (+R finalize in blocks 0..15) ----------------
__global__ void __launch_bounds__(256) bern_kernel() {
    if (blockIdx.x < 16) {
        int idx = blockIdx.x * 256 + threadIdx.x;   // 0..4095
        int i = idx >> 6, jj = idx & 63;
        double s = 0.0;
        for (int b = 0; b < 16; b++) s += (double)g_Rpart[b * 4096 + idx];
        s += (2048.0 / 2049.0) * g_xbard[i] * g_xbard[jj];
        if (i == jj) s += 0.5;
        g_R[idx] = (float)s;
    }
    int gid = blockIdx.x * 256 + threadIdx.x;   // 262144 = 32768 cols * 8
    int part = gid & 7;
    int col = gid >> 3;                         // (p*16+s)*64 + j
    int j = col & 63, p = col >> 10;
    unsigned k0 = g_keys[0], k1 = g_keys[1];
    const float* pr = g_probs + p * 4096;
    int i0 = part * 8;
    unsigned base = (unsigned)((col >> 6) * 4096 + i0 * 64 + j);
    unsigned long long m = 0ull;
#pragma unroll
    for (int r = 0; r < 8; r++) {
        unsigned bits = jax_bits32(k0, k1, base + (unsigned)(r * 64));
        if (u01f(bits) < pr[(i0 + r) * 64 + j]) m |= 1ull << (i0 + r);
    }
    m |= __shfl_xor_sync(0xffffffffu, m, 1);
    m |= __shfl_xor_sync(0xffffffffu, m, 2);
    m |= __shfl_xor_sync(0xffffffffu, m, 4);
    if (part == 0) g_cols[col] = m;
}

// ---------------- launch 4 (profiled): BGe small (m <= CAP), proven ----------------
// score_j = lg(l) - 0.5*logdet(R[S,S]) - 0.5*(2051+l)*log(schur pivot of j)
__global__ void __launch_bounds__(256) bge_small_kernel(
        const unsigned long long* __restrict__ cols,
        double* __restrict__ ns, int ntask) {
    __shared__ float sT[8][TRI_CAP];
    __shared__ unsigned char sidx[8][64];
    int w = threadIdx.x >> 5, lane = threadIdx.x & 31;
    int task = blockIdx.x * 8 + w;
    if (task >= ntask) return;
    unsigned long long mask = cols[task];
    int l = __popcll(mask);
    int m = l + 1;
    if (m > CAP) return;                 // rare: bge_big handles
    int j = task & 63;
    unsigned char* idx = sidx[w];
    if (lane == 0) {
        unsigned long long mm = mask; int c = 0;
        while (mm) { int b = __ffsll(mm) - 1; idx[c++] = (unsigned char)b; mm &= mm - 1; }
        idx[l] = (unsigned char)j;
    }
    __syncwarp();
    float* T = sT[w];
    {
        int base = 0;
        for (int a = 0; a < m; a++) {
            const float* Rrow = g_R + (int)idx[a] * 64;
            for (int b = a + lane; b < m; b += 32) T[base + b - a] = Rrow[idx[b]];
            base += m - a;
        }
    }
    __syncwarp();
    float logA = 0.f, lastpiv = 1.f;
    int basek = 0;
    int k = 0;
    if (m <= 33) {
        // single-column rank-2 path
        while (k + 1 < m) {
            int basek1 = basek + (m - k);
            float pivk = T[basek];
            float inv = 1.0f / pivk;
            float akk1 = T[basek + 1];
            int ja0 = k + 1 + lane;
            if (ja0 < m) {
                float t = T[basek + ja0 - k] * inv;
                T[basek1 + ja0 - (k + 1)] -= akk1 * t;
            }
            __syncwarp();
            float pivk1 = T[basek1];
            float inv2 = 1.0f / pivk1;
            if (lane == 0) {
                logA += logf(pivk);
                if (k + 1 < m - 1) logA += logf(pivk1);
                else lastpiv = pivk1;
            }
            int jb0 = k + 2 + lane;
            float t0 = 0.f, s0 = 0.f;
            if (jb0 < m) {
                t0 = T[basek + jb0 - k] * inv;
                s0 = T[basek1 + jb0 - k - 1] * inv2;
            }
            int bi = basek1 + (m - k - 1);
            for (int i = k + 2; i < m; i++) {
                float aki = T[basek + i - k];
                float bki = T[basek1 + i - k - 1];
                if (jb0 >= i && jb0 < m) {
                    float x = T[bi + jb0 - i];
                    x -= aki * t0;
                    x -= bki * s0;
                    T[bi + jb0 - i] = x;
                }
                bi += m - i;
            }
            basek = basek1 + (m - k - 1);
            k += 2;
            __syncwarp();
        }
    } else {
        // dual-column rank-2 path (m in 34..52)
        while (k + 1 < m) {
            int basek1 = basek + (m - k);
            float pivk = T[basek];
            float inv = 1.0f / pivk;
            float akk1 = T[basek + 1];
            int ja0 = k + 1 + lane, ja1 = ja0 + 32;
            if (ja0 < m) {
                float t = T[basek + ja0 - k] * inv;
                T[basek1 + ja0 - (k + 1)] -= akk1 * t;
            }
            if (ja1 < m) {
                float t = T[basek + ja1 - k] * inv;
                T[basek1 + ja1 - (k + 1)] -= akk1 * t;
            }
            __syncwarp();
            float pivk1 = T[basek1];
            float inv2 = 1.0f / pivk1;
            if (lane == 0) {
                logA += logf(pivk);
                if (k + 1 < m - 1) logA += logf(pivk1);
                else lastpiv = pivk1;
            }
            int jb0 = k + 2 + lane, jb1 = jb0 + 32;
            float t0 = 0.f, s0 = 0.f, t1 = 0.f, s1 = 0.f;
            if (jb0 < m) {
                t0 = T[basek + jb0 - k] * inv;
                s0 = T[basek1 + jb0 - k - 1] * inv2;
            }
            if (jb1 < m) {
                t1 = T[basek + jb1 - k] * inv;
                s1 = T[basek1 + jb1 - k - 1] * inv2;
            }
            int bi = basek1 + (m - k - 1);
            for (int i = k + 2; i < m; i++) {
                float aki = T[basek + i - k];
                float bki = T[basek1 + i - k - 1];
                if (jb0 >= i && jb0 < m) {
                    float x = T[bi + jb0 - i];
                    x -= aki * t0;
                    x -= bki * s0;
                    T[bi + jb0 - i] = x;
                }
                if (jb1 >= i && jb1 < m) {
                    float x = T[bi + jb1 - i];
                    x -= aki * t1;
                    x -= bki * s1;
                    T[bi + jb1 - i] = x;
                }
                bi += m - i;
            }
            basek = basek1 + (m - k - 1);
            k += 2;
            __syncwarp();
        }
    }
    if (k < m) lastpiv = T[basek];       // odd m: last pivot untouched by pairs
    if (lane == 0) {
        ns[task] = g_lgtab[l] - 0.5 * (double)logA
                 - 0.5 * (2051.0 + (double)l) * log((double)lastpiv);
    }
}

// ---------------- fallback: BGe big (m > CAP only) ----------------
__global__ void __launch_bounds__(128) bge_big_kernel(
        const unsigned long long* __restrict__ cols,
        double* __restrict__ ns, int ntask) {
    __shared__ float sT[4][2080];
    __shared__ unsigned char sidx[4][64];
    int w = threadIdx.x >> 5, lane = threadIdx.x & 31;
    int task = blockIdx.x * 4 + w;
    if (task >= ntask) return;
    unsigned long long mask = cols[task];
    int l = __popcll(mask);
    int m = l + 1;
    if (m <= CAP) return;
    int j = task & 63;
    unsigned char* idx = sidx[w];
    if (lane == 0) {
        unsigned long long mm = mask; int c = 0;
        while (mm) { int b = __ffsll(mm) - 1; idx[c++] = (unsigned char)b; mm &= mm - 1; }
        idx[l] = (unsigned char)j;
    }
    __syncwarp();
    float* T = sT[w];
    {
        int base = 0;
        for (int a = 0; a < m; a++) {
            const float* Rrow = g_R + (int)idx[a] * 64;
            for (int b = a + lane; b < m; b += 32) T[base + b - a] = Rrow[idx[b]];
            base += m - a;
        }
    }
    __syncwarp();
    float logA = 0.f, lastpiv = 1.f;
    int basek = 0;
    int k = 0;
    for (; k < m - 33; k++) {
        float piv = T[basek];
        if (lane == 0) logA += logf(piv);
        float inv = 1.0f / piv;
        int j0 = k + 1 + lane, j1 = j0 + 32;
        float t0 = T[basek + 1 + lane] * inv;
        float t1 = (j1 < m) ? T[basek + 33 + lane] * inv : 0.f;
        int bi = basek + (m - k);
        for (int i = k + 1; i < m; i++) {
            float aki = T[basek + i - k];
            if (j0 >= i)           T[bi + j0 - i] -= aki * t0;
            if (j1 >= i && j1 < m) T[bi + j1 - i] -= aki * t1;
            bi += m - i;
        }
        basek += m - k;
        __syncwarp();
    }
    for (; k < m; k++) {
        float piv = T[basek];
        if (lane == 0) {
            if (k < m - 1) logA += logf(piv);
            else lastpiv = piv;
        }
        int rem = m - 1 - k;
        if (rem > 0) {
            float inv = 1.0f / piv;
            int j0 = k + 1 + lane;
            float t0 = (lane < rem) ? T[basek + 1 + lane] * inv : 0.f;
            int bi = basek + (m - k);
            for (int i = k + 1; i < m; i++) {
                float aki = T[basek + i - k];
                if (j0 >= i && j0 < m) T[bi + j0 - i] -= aki * t0;
                bi += m - i;
            }
        }
        basek += m - k;
        __syncwarp();
    }
    if (lane == 0) {
        ns[task] = g_lgtab[l] - 0.5 * (double)logA
                 - 0.5 * (2051.0 + (double)l) * log((double)lastpiv);
    }
}

// ---------------- fused reduce + softmax (MC): block per particle ----------------
__global__ void __launch_bounds__(512) redsoft_kernel() {
    __shared__ double sv[16];
    int p = blockIdx.x;
    int s = threadIdx.x >> 5, lane = threadIdx.x & 31;
    const double* nsg = g_ns + (p * 16 + s) * 64;
    double a = nsg[lane] + nsg[lane + 32];
    for (int o = 16; o > 0; o >>= 1) a += __shfl_xor_sync(0xffffffffu, a, o);
    if (lane == 0) sv[s] = a;
    __syncthreads();
    if (threadIdx.x < 32) {
        double v = (lane < 16) ? sv[lane] : -1e300;
        double mx = v;
        for (int o = 16; o > 0; o >>= 1) mx = fmax(mx, __shfl_xor_sync(0xffffffffu, mx, o));
        double e = (lane < 16) ? exp(v - mx) : 0.0;
        double sm = e;
        for (int o = 16; o > 0; o >>= 1) sm += __shfl_xor_sync(0xffffffffu, sm, o);
        if (lane < 16) g_w[p * 16 + lane] = e / sm;
    }
}

// hard graphs: deterministic tree reduce straight into the float output slot
__global__ void reduce64h_kernel(const double* __restrict__ ns, float* __restrict__ out) {
    __shared__ double s[64];
    int g = blockIdx.x, t = threadIdx.x;
    s[t] = ns[g * 64 + t];
    __syncthreads();
    for (int st = 32; st > 0; st >>= 1) {
        if (t < st) s[t] += s[t + st];
        __syncthreads();
    }
    if (t == 0) out[OFF_LOGP + g] = (float)s[0];
}

// ---------------- B ----------------
__global__ void B_kernel() {
    int idx = blockIdx.x * blockDim.x + threadIdx.x;
    int j = idx & 63, i = (idx >> 6) & 63, p = idx >> 12;
    float pr = g_probs[p * 4096 + i * 64 + j];
    double ws = 0.0;
    for (int s = 0; s < 16; s++)
        if ((g_cols[(p * 16 + s) * 64 + j] >> i) & 1ull) ws += g_w[p * 16 + s];
    float B = 0.f;
    if (i != j)
        B = 0.2f * ((float)ws - pr) + 0.2f * pr * (1.f - pr) * (float)g_logitpe;
    g_B[idx] = B;
}

// ---------------- grads (fused u/v) ----------------
__global__ void gradufv_kernel(const float* __restrict__ z) {
    int bb = blockIdx.x;
    int k = threadIdx.x;
    if (bb < 2048) {
        int p = bb >> 6, i = bb & 63;
        const float* Bp = g_B + p * 4096 + i * 64;
        const float* zp = z + p * 8192;
        float acc = 0.f;
        for (int j = 0; j < 64; j++) acc = fmaf(Bp[j], zp[(j * 64 + k) * 2 + 1], acc);
        float u = zp[(i * 64 + k) * 2];
        g_grads[(bb * 64 + k) * 2] = acc - 64.f * u;
    } else {
        int b2 = bb - 2048;
        int p = b2 >> 6, j = b2 & 63;
        const float* Bp = g_B + p * 4096;
        const float* zp = z + p * 8192;
        float acc = 0.f;
        for (int i = 0; i < 64; i++) acc = fmaf(Bp[i * 64 + j], zp[(i * 64 + k) * 2], acc);
        float v = zp[(j * 64 + k) * 2 + 1];
        g_grads[((p * 64 + j) * 64 + k) * 2 + 1] = acc - 64.f * v;
    }
}

// ---------------- SVGD Kmat: f32, warp per pair, 256 blocks ----------------
// f32 matches the reference (zf/sq/exp are all f32 there). Off-diagonal K ~ e^-51
// so rounding perturbs z_new by ~1e-23; diagonal is exactly 1 (d = 0).
__global__ void __launch_bounds__(128) kmat_kernel(const float* __restrict__ z) {
    int pair = blockIdx.x * 4 + (threadIdx.x >> 5);  // 0..1023
    int lane = threadIdx.x & 31;
    int p = pair >> 5, q = pair & 31;
    const float* a = z + p * 8192;
    const float* b = z + q * 8192;
    float sq0 = 0.f, sq1 = 0.f;
    for (int t = lane; t < 8192; t += 64) {
        float d0 = a[t] - b[t];
        float d1 = a[t + 32] - b[t + 32];
        sq0 = fmaf(d0, d0, sq0);
        sq1 = fmaf(d1, d1, sq1);
    }
    float sq = sq0 + sq1;
    for (int o = 16; o > 0; o >>= 1) sq += __shfl_xor_sync(0xffffffffu, sq, o);
    if (lane == 0) g_Kmat[p * 32 + q] = expf(-sq * 0.2f);
}

__global__ void znew_kernel(const float* __restrict__ z, float* __restrict__ out) {
    int p = blockIdx.x;
    __shared__ float kr[32];
    __shared__ float rowsum;
    if (threadIdx.x < 32) kr[threadIdx.x] = g_Kmat[p * 32 + threadIdx.x];
    __syncthreads();
    if (threadIdx.x == 0) {
        float s = 0.f;
        for (int q = 0; q < 32; q++) s += kr[q];
        rowsum = s;
    }
    __syncthreads();
    for (int d = threadIdx.x; d < 8192; d += blockDim.x) {
        float ag = 0.f, az = 0.f;
        for (int q = 0; q < 32; q++) {
            float kk = kr[q];
            ag = fmaf(kk, g_grads[q * 8192 + d], ag);
            az = fmaf(kk, z[q * 8192 + d], az);
        }
        float zp = z[p * 8192 + d];
        float rep = (-2.0f / 5.0f) * (az - zp * rowsum);
        float zn = zp + 0.005f * ((ag + rep) * (1.0f / 32.0f));
        out[OFF_ZNEW + p * 8192 + d] = zn;
    }
}

// ---------------- hard graphs: ILPx4 (thread=i, 4 j's), ballot masks ----------------
__global__ void s2_kernel(float* __restrict__ out) {
    __shared__ unsigned int mparts[2][4];
    int b = blockIdx.x;
    int p = b >> 4, jg = b & 15;
    int i = threadIdx.x;                 // 0..63, two warps
    const float* zn = out + OFF_ZNEW + p * 8192;
    int j0 = jg * 4;
    double acc0 = 0.0, acc1 = 0.0, acc2 = 0.0, acc3 = 0.0;
    for (int k = 0; k < 64; k++) {
        double ui = (double)zn[(i * 64 + k) * 2];
        acc0 += ui * (double)zn[((j0 + 0) * 64 + k) * 2 + 1];
        acc1 += ui * (double)zn[((j0 + 1) * 64 + k) * 2 + 1];
        acc2 += ui * (double)zn[((j0 + 2) * 64 + k) * 2 + 1];
        acc3 += ui * (double)zn[((j0 + 3) * 64 + k) * 2 + 1];
    }
    double accs[4] = {acc0, acc1, acc2, acc3};
#pragma unroll
    for (int r = 0; r < 4; r++) {
        int j = j0 + r;
        bool edge = (i != j && accs[r] > 0.0);
        out[OFF_GHARD + p * 4096 + i * 64 + j] = edge ? 1.f : 0.f;
        unsigned bal = __ballot_sync(0xffffffffu, edge);
        if ((i & 31) == 0) mparts[i >> 5][r] = bal;
    }
    __syncthreads();
    if (i < 4)
        g_colsh[p * 64 + j0 + i] = (unsigned long long)mparts[0][i]
                                 | ((unsigned long long)mparts[1][i] << 32);
}

// ---------------- encoder L1 ----------------
__global__ void enc0_kernel(const float* __restrict__ out,
                            const float* __restrict__ ew0,
                            const float* __restrict__ eb0) {
    int gw = blockIdx.x * 8 + (threadIdx.x >> 5);
    if (gw >= 640) return;
    int p = gw / 20, o = gw % 20;
    int lane = threadIdx.x & 31;
    const float* gp = out + OFF_GHARD + p * 4096;
    float acc = 0.f;
    for (int t = lane; t < 4096; t += 32) acc = fmaf(gp[t], ew0[t * 20 + o], acc);
    for (int of = 16; of > 0; of >>= 1) acc += __shfl_xor_sync(0xffffffffu, acc, of);
    if (lane == 0) g_h0[p * 20 + o] = fmaxf(0.f, acc + eb0[o]);
}

// ---------------- remaining MLP layers: one block per particle ----------------
__global__ void __launch_bounds__(64) mlp_kernel(float* __restrict__ out,
    const float* ew1, const float* eb1, const float* ew2, const float* eb2,
    const float* mw0, const float* mb0, const float* mw1, const float* mb1,
    const float* lw0, const float* lb0, const float* lw1, const float* lb1,
    const float* dw0, const float* db0, const float* dw1, const float* db1,
    const float* dw2, const float* db2) {
    __shared__ float h0s[20];
    __shared__ float h1[64];
    __shared__ float h2[64];
    __shared__ float amu[64];
    __shared__ float qmu[64];
    __shared__ float alv[64];
    __shared__ float qz[64];
    __shared__ float hd0[10];
    __shared__ float hd1[128];
    int p = blockIdx.x, o = threadIdx.x;
    if (o < 20) h0s[o] = g_h0[p * 20 + o];
    __syncthreads();
    {
        float a = eb1[o];
        for (int t = 0; t < 20; t++) a = fmaf(h0s[t], ew1[t * 64 + o], a);
        h1[o] = fmaxf(0.f, a);
    }
    __syncthreads();
    {
        float a = eb2[o];
        for (int t = 0; t < 64; t++) a = fmaf(h1[t], ew2[t * 64 + o], a);
        h2[o] = fmaxf(0.f, a);
    }
    __syncthreads();
    {
        float a = mb0[o];
        for (int t = 0; t < 64; t++) a = fmaf(h2[t], mw0[t * 64 + o], a);
        amu[o] = fmaxf(0.f, a);
        float b = lb0[o];
        for (int t = 0; t < 64; t++) b = fmaf(h2[t], lw0[t * 64 + o], b);
        alv[o] = fmaxf(0.f, b);
    }
    __syncthreads();
    {
        float a = mb1[o];
        for (int t = 0; t < 64; t++) a = fmaf(amu[t], mw1[t * 64 + o], a);
        qmu[o] = a;
        out[OFF_QMU + p * 64 + o] = a;
        float b = lb1[o];
        for (int t = 0; t < 64; t++) b = fmaf(alv[t], lw1[t * 64 + o], b);
        out[OFF_QLV + p * 64 + o] = b;
        float eps = jax_normal(jax_bits32(g_keys[2], g_keys[3], (unsigned)(p * 64 + o)));
        float q = qmu[o] + eps * expf(0.5f * b);
        out[OFF_QZ + p * 64 + o] = q;
        qz[o] = q;
    }
    __syncthreads();
    if (o < 10) {
        float a = db0[o];
        for (int t = 0; t < 64; t++) a = fmaf(qz[t], dw0[t * 10 + o], a);
        hd0[o] = fmaxf(0.f, a);
    }
    __syncthreads();
#pragma unroll
    for (int g = 0; g < 2; g++) {
        int oo = o + g * 64;
        float a = db1[oo];
        for (int t = 0; t < 10; t++) a = fmaf(hd0[t], dw1[t * 128 + oo], a);
        hd1[oo] = fmaxf(0.f, a);
    }
    __syncthreads();
#pragma unroll
    for (int g = 0; g < 2; g++) {
        int oo = o + g * 64;
        float a = db2[oo];
        for (int t = 0; t < 128; t++) a = fmaf(hd1[t], dw2[t * 128 + oo], a);
        out[OFF_RECONS + p * 128 + oo] = a;
    }
}

// ---------------- launch ----------------
extern "C" void kernel_launch(void* const* d_in, const int* in_sizes, int n_in,
                              void* d_out, int out_size) {
    const float* z_gt = (const float*)d_in[0];
    const float* z0   = (const float*)d_in[1];
    const float* ew0 = (const float*)d_in[2];  const float* eb0 = (const float*)d_in[3];
    const float* ew1 = (const float*)d_in[4];  const float* eb1 = (const float*)d_in[5];
    const float* ew2 = (const float*)d_in[6];  const float* eb2 = (const float*)d_in[7];
    const float* mw0 = (const float*)d_in[8];  const float* mb0 = (const float*)d_in[9];
    const float* mw1 = (const float*)d_in[10]; const float* mb1 = (const float*)d_in[11];
    const float* lw0 = (const float*)d_in[12]; const float* lb0 = (const float*)d_in[13];
    const float* lw1 = (const float*)d_in[14]; const float* lb1 = (const float*)d_in[15];
    const float* dw0 = (const float*)d_in[16]; const float* db0 = (const float*)d_in[17];
    const float* dw1 = (const float*)d_in[18]; const float* db1 = (const float*)d_in[19];
    const float* dw2 = (const float*)d_in[20]; const float* db2 = (const float*)d_in[21];
    const int*   seed = (const int*)d_in[22];
    float* out = (float*)d_out;

    unsigned long long* colsMC; cudaGetSymbolAddress((void**)&colsMC, g_cols);
    unsigned long long* colsH;  cudaGetSymbolAddress((void**)&colsH,  g_colsh);
    double* nsMC;  cudaGetSymbolAddress((void**)&nsMC,  g_ns);
    double* nsH;   cudaGetSymbolAddress((void**)&nsH,   g_nsh);

    scores_kernel<<<512, 64>>>(z0, z_gt, seed);                // 1: probs + xbar + init
    Rtile_kernel<<<16, 256>>>(z_gt);                           // 2: R partials
    bern_kernel<<<1024, 256>>>();                              // 3: sampling + R finalize
    bge_small_kernel<<<NG * 64 / 8, 256>>>(colsMC, nsMC, NG * 64);  // 4 (profiled)
    bge_big_kernel<<<NG * 64 / 4, 128>>>(colsMC, nsMC, NG * 64);
    redsoft_kernel<<<Pn, 512>>>();
    B_kernel<<<512, 256>>>();
    gradufv_kernel<<<4096, 64>>>(z0);
    kmat_kernel<<<256, 128>>>(z0);
    znew_kernel<<<Pn, 256>>>(z0, out);
    s2_kernel<<<512, 64>>>(out);
    bge_small_kernel<<<Pn * 64 / 8, 256>>>(colsH, nsH, Pn * 64);
    bge_big_kernel<<<Pn * 64 / 4, 128>>>(colsH, nsH, Pn * 64);
    reduce64h_kernel<<<Pn, 64>>>(nsH, out);
    enc0_kernel<<<80, 256>>>(out, ew0, eb0);
    mlp_kernel<<<Pn, 64>>>(out, ew1, eb1, ew2, eb2,
                           mw0, mb0, mw1, mb1, lw0, lb0, lw1, lb1,
                           dw0, db0, dw1, db1, dw2, db2);
}

// round 14
// speedup vs baseline: 1.6842x; 1.0668x over previous
#include <cuda_runtime.h>
#include <cuda_bf16.h>
#include <math.h>
#include <stdint.h>

// ---------------- problem constants ----------------
#define Dn    64
#define Pn    32
#define NMC   16
#define NG    512           // Pn*NMC
#define NOBS  2048
#define CAP   52            // max m handled by bge_small (l <= 51)
#define TRI_CAP 1378        // CAP*(CAP+1)/2
// output layout (floats)
#define OFF_RECONS 0
#define OFF_LOGP   4096
#define OFF_QZ     4128
#define OFF_QMU    6176
#define OFF_QLV    8224
#define OFF_GHARD  10272
#define OFF_ZNEW   141344

// ---------------- device scratch ----------------
static __device__ double             g_xbard[Dn];
static __device__ float              g_Rpart[16 * 4096];
static __device__ float              g_R[Dn * Dn];
static __device__ float              g_probs[Pn * Dn * Dn];
static __device__ unsigned long long g_cols[NG * Dn];
static __device__ unsigned long long g_colsh[Pn * Dn];
static __device__ double             g_ns[NG * Dn];
static __device__ double             g_nsh[Pn * Dn];
static __device__ double             g_w[NG];
static __device__ float              g_B[Pn * Dn * Dn];
static __device__ float              g_grads[Pn * Dn * Dn * 2];
static __device__ float              g_Kmat[Pn * Pn];
static __device__ unsigned int       g_keys[4];
static __device__ double             g_lgtab[64];
static __device__ double             g_logitpe;
static __device__ float              g_h0[Pn * 20];

// ---------------- threefry2x32 (JAX-exact) ----------------
__device__ __forceinline__ void tf2x32(unsigned k0, unsigned k1,
                                       unsigned x0, unsigned x1,
                                       unsigned &o0, unsigned &o1) {
    unsigned ks0 = k0, ks1 = k1, ks2 = k0 ^ k1 ^ 0x1BD11BDAu;
    x0 += ks0; x1 += ks1;
#define TFR(r) { x0 += x1; x1 = __funnelshift_l(x1, x1, r); x1 ^= x0; }
    TFR(13) TFR(15) TFR(26) TFR(6)   x0 += ks1; x1 += ks2 + 1u;
    TFR(17) TFR(29) TFR(16) TFR(24)  x0 += ks2; x1 += ks0 + 2u;
    TFR(13) TFR(15) TFR(26) TFR(6)   x0 += ks0; x1 += ks1 + 3u;
    TFR(17) TFR(29) TFR(16) TFR(24)  x0 += ks1; x1 += ks2 + 4u;
    TFR(13) TFR(15) TFR(26) TFR(6)   x0 += ks2; x1 += ks0 + 5u;
#undef TFR
    o0 = x0; o1 = x1;
}

__device__ __forceinline__ unsigned jax_bits32(unsigned k0, unsigned k1, unsigned idx) {
    unsigned o0, o1;
    tf2x32(k0, k1, 0u, idx, o0, o1);
    return o0 ^ o1;
}

__device__ __forceinline__ float u01f(unsigned b) {
    return __uint_as_float((b >> 9) | 0x3f800000u) - 1.0f;
}

__device__ __forceinline__ float jax_normal(unsigned bits) {
    const float lo = -0.99999994f;
    float f = u01f(bits);
    float u = fmaxf(lo, fmaf(f, 2.0f, lo));
    float w = -log1pf(-u * u);
    float p;
    if (w < 5.0f) {
        w -= 2.5f;
        p = 2.81022636e-08f;
        p = fmaf(p, w, 3.43273939e-07f);
        p = fmaf(p, w, -3.5233877e-06f);
        p = fmaf(p, w, -4.39150654e-06f);
        p = fmaf(p, w, 0.00021858087f);
        p = fmaf(p, w, -0.00125372503f);
        p = fmaf(p, w, -0.00417768164f);
        p = fmaf(p, w, 0.246640727f);
        p = fmaf(p, w, 1.50140941f);
    } else {
        w = sqrtf(w) - 3.0f;
        p = -0.000200214257f;
        p = fmaf(p, w, 0.000100950558f);
        p = fmaf(p, w, 0.00134934322f);
        p = fmaf(p, w, -0.00367342844f);
        p = fmaf(p, w, 0.00573950773f);
        p = fmaf(p, w, -0.0076224613f);
        p = fmaf(p, w, 0.00943887047f);
        p = fmaf(p, w, 1.00167406f);
        p = fmaf(p, w, 2.83297682f);
    }
    return 1.4142135381698608f * (p * u);
}

// ---------------- launch 1: scores ILPx4 (+init +xbar) ----------------
__global__ void scores_kernel(const float* __restrict__ z,
                              const float* __restrict__ zgt,
                              const int* __restrict__ seed_ptr) {
    __shared__ double sx[64];
    int b = blockIdx.x;
    int p = b >> 4, ig = b & 15;
    int j = threadIdx.x;
    if (b < 64) {            // xbar duty: block b -> column b
        int col = b;
        double a = 0.0;
        int n0 = j * 32;
        for (int n = n0; n < n0 + 32; n++) a += (double)zgt[n * 64 + col];
        sx[j] = a;
        __syncthreads();
        for (int st = 32; st > 0; st >>= 1) {
            if (j < st) sx[j] += sx[j + st];
            __syncthreads();
        }
        if (j == 0) g_xbard[col] = sx[0] / 2048.0;
    }
    if (b == 0) {
        if (j == 0) {
            unsigned seed = (unsigned)seed_ptr[0];
            unsigned a0, a1, b0, b1;
            tf2x32(0u, seed, 0u, 0u, a0, a1);
            tf2x32(0u, seed, 0u, 1u, b0, b1);   // sk
            unsigned c0, c1, d0, d1;
            tf2x32(a0, a1, 0u, 0u, c0, c1);
            tf2x32(a0, a1, 0u, 1u, d0, d1);     // rk
            g_keys[0] = b0; g_keys[1] = b1;
            g_keys[2] = d0; g_keys[3] = d1;
            double pe = 4.0 / 63.0;
            g_logitpe = log(pe) - log1p(-pe);
        }
        const double LOG_PI   = 1.1447298858494001741;
        const double LOG_HALF = -0.6931471805599453094;
        double l = (double)j;
        g_lgtab[j] = -0.5 * log(2049.0)
                   + lgamma(0.5 * (2051.0 + l)) - lgamma(0.5 * (3.0 + l))
                   - 1024.0 * LOG_PI
                   + 0.5 * (3.0 + 2.0 * l) * LOG_HALF;
    }
    const float* zp = z + p * 8192;
    int i0 = ig * 4;
    double acc0 = 0.0, acc1 = 0.0, acc2 = 0.0, acc3 = 0.0;
    for (int k = 0; k < 64; k++) {
        double vj = (double)zp[(j * 64 + k) * 2 + 1];
        acc0 += (double)zp[((i0 + 0) * 64 + k) * 2] * vj;
        acc1 += (double)zp[((i0 + 1) * 64 + k) * 2] * vj;
        acc2 += (double)zp[((i0 + 2) * 64 + k) * 2] * vj;
        acc3 += (double)zp[((i0 + 3) * 64 + k) * 2] * vj;
    }
    double accs[4] = {acc0, acc1, acc2, acc3};
#pragma unroll
    for (int r = 0; r < 4; r++) {
        int i = i0 + r;
        float sc = (float)accs[r];
        float tl = 0.2f * sc;
        float pr = (i == j) ? 0.f : (0.5f * tanhf(0.5f * tl) + 0.5f);  // XLA logistic
        g_probs[p * 4096 + i * 64 + j] = pr;
    }
}

// ---------------- launch 2: R tile partials (16 blocks x 256) ----------------
__global__ void Rtile_kernel(const float* __restrict__ zgt) {
    __shared__ float xs[128 * 64];
    int tid = threadIdx.x;
    int nb = blockIdx.x * 128;
    for (int idx = tid; idx < 128 * 64; idx += 256) {
        int n = idx >> 6, c = idx & 63;
        xs[idx] = zgt[(nb + n) * 64 + c] - (float)g_xbard[c];
    }
    __syncthreads();
    int i0 = (tid >> 4) << 2, j0 = (tid & 15) << 2;
    float acc[4][4];
#pragma unroll
    for (int r = 0; r < 4; r++)
#pragma unroll
        for (int c = 0; c < 4; c++) acc[r][c] = 0.f;
    for (int n = 0; n < 128; n++) {
        float4 a = *reinterpret_cast<const float4*>(&xs[n * 64 + i0]);
        float4 b = *reinterpret_cast<const float4*>(&xs[n * 64 + j0]);
        float ar[4] = {a.x, a.y, a.z, a.w};
        float br[4] = {b.x, b.y, b.z, b.w};
#pragma unroll
        for (int r = 0; r < 4; r++)
#pragma unroll
            for (int c = 0; c < 4; c++) acc[r][c] = fmaf(ar[r], br[c], acc[r][c]);
    }
    float* out = g_Rpart + blockIdx.x * 4096;
#pragma unroll
    for (int r = 0; r < 4; r++)
#pragma unroll
        for (int c = 0; c < 4; c++) out[(i0 + r) * 64 + (j0 + c)] = acc[r][c];
}

// ---------------- launch 3: bernoulli (+R finalize in blocks 0..15) ----------------
__global__ void __launch_bounds__(256) bern_kernel() {
    if (blockIdx.x < 16) {
        int idx = blockIdx.x * 256 + threadIdx.x;   // 0..4095
        int i = idx >> 6, jj = idx & 63;
        double s = 0.0;
        for (int b = 0; b < 16; b++) s += (double)g_Rpart[b * 4096 + idx];
        s += (2048.0 / 2049.0) * g_xbard[i] * g_xbard[jj];
        if (i == jj) s += 0.5;
        g_R[idx] = (float)s;
    }
    int gid = blockIdx.x * 256 + threadIdx.x;   // 262144 = 32768 cols * 8
    int part = gid & 7;
    int col = gid >> 3;                         // (p*16+s)*64 + j
    int j = col & 63, p = col >> 10;
    unsigned k0 = g_keys[0], k1 = g_keys[1];
    const float* pr = g_probs + p * 4096;
    int i0 = part * 8;
    unsigned base = (unsigned)((col >> 6) * 4096 + i0 * 64 + j);
    unsigned long long m = 0ull;
#pragma unroll
    for (int r = 0; r < 8; r++) {
        unsigned bits = jax_bits32(k0, k1, base + (unsigned)(r * 64));
        if (u01f(bits) < pr[(i0 + r) * 64 + j]) m |= 1ull << (i0 + r);
    }
    m |= __shfl_xor_sync(0xffffffffu, m, 1);
    m |= __shfl_xor_sync(0xffffffffu, m, 2);
    m |= __shfl_xor_sync(0xffffffffu, m, 4);
    if (part == 0) g_cols[col] = m;
}

// ---------------- launch 4 (profiled): BGe small (m <= CAP), rank-4 panels ----------------
// score_j = lg(l) - 0.5*logdet(R[S,S]) - 0.5*(2051+l)*log(schur pivot of j)
// Rank-4 panel: factor rows k..k+3 sequentially (lane-parallel), then fused
// 4x rank-1 trailing update. Every FFMA operand-identical to sequential rank-1.
__global__ void __launch_bounds__(256) bge_small_kernel(
        const unsigned long long* __restrict__ cols,
        double* __restrict__ ns, int ntask) {
    __shared__ float sT[8][TRI_CAP];
    __shared__ unsigned char sidx[8][64];
    int w = threadIdx.x >> 5, lane = threadIdx.x & 31;
    int task = blockIdx.x * 8 + w;
    if (task >= ntask) return;
    unsigned long long mask = cols[task];
    int l = __popcll(mask);
    int m = l + 1;
    if (m > CAP) return;                 // rare: bge_big handles
    int j = task & 63;
    unsigned char* idx = sidx[w];
    if (lane == 0) {
        unsigned long long mm = mask; int c = 0;
        while (mm) { int b = __ffsll(mm) - 1; idx[c++] = (unsigned char)b; mm &= mm - 1; }
        idx[l] = (unsigned char)j;
    }
    __syncwarp();
    float* T = sT[w];
    {
        int base = 0;
        for (int a = 0; a < m; a++) {
            const float* Rrow = g_R + (int)idx[a] * 64;
            for (int b = a + lane; b < m; b += 32) T[base + b - a] = Rrow[idx[b]];
            base += m - a;
        }
    }
    __syncwarp();
    float logA = 0.f, lastpiv = 1.f;
    int basek = 0;
    int k = 0;
    if (m <= 33) {
        // ---- single-column rank-4 panels ----
        while (k + 3 < m) {
            int b0 = basek;
            int b1 = b0 + (m - k);
            int b2 = b1 + (m - k - 1);
            int b3 = b2 + (m - k - 2);
            float piv0 = T[b0]; float inv0 = 1.0f / piv0;
            float a01 = T[b0 + 1];
            {
                int jj = k + 1 + lane;
                if (jj < m) {
                    float t = T[b0 + jj - k] * inv0;
                    T[b1 + jj - k - 1] -= a01 * t;
                }
            }
            __syncwarp();
            float piv1 = T[b1]; float inv1 = 1.0f / piv1;
            float a02 = T[b0 + 2], a12 = T[b1 + 1];
            {
                int jj = k + 2 + lane;
                if (jj < m) {
                    float t0 = T[b0 + jj - k] * inv0;
                    float x = T[b2 + jj - k - 2];
                    x -= a02 * t0;
                    float t1 = T[b1 + jj - k - 1] * inv1;
                    x -= a12 * t1;
                    T[b2 + jj - k - 2] = x;
                }
            }
            __syncwarp();
            float piv2 = T[b2]; float inv2 = 1.0f / piv2;
            float a03 = T[b0 + 3], a13 = T[b1 + 2], a23 = T[b2 + 1];
            {
                int jj = k + 3 + lane;
                if (jj < m) {
                    float t0 = T[b0 + jj - k] * inv0;
                    float x = T[b3 + jj - k - 3];
                    x -= a03 * t0;
                    float t1 = T[b1 + jj - k - 1] * inv1;
                    x -= a13 * t1;
                    float t2 = T[b2 + jj - k - 2] * inv2;
                    x -= a23 * t2;
                    T[b3 + jj - k - 3] = x;
                }
            }
            __syncwarp();
            float piv3 = T[b3]; float inv3 = 1.0f / piv3;
            if (lane == 0) {
                logA += logf(piv0);
                logA += logf(piv1);
                logA += logf(piv2);
                if (k + 3 < m - 1) logA += logf(piv3);
                else lastpiv = piv3;
            }
            int jb = k + 4 + lane;
            float t0 = 0.f, t1 = 0.f, t2 = 0.f, t3 = 0.f;
            if (jb < m) {
                t0 = T[b0 + jb - k] * inv0;
                t1 = T[b1 + jb - k - 1] * inv1;
                t2 = T[b2 + jb - k - 2] * inv2;
                t3 = T[b3 + jb - k - 3] * inv3;
            }
            int bi = b3 + (m - k - 3);
            for (int i = k + 4; i < m; i++) {
                float a0 = T[b0 + i - k];
                float a1 = T[b1 + i - k - 1];
                float a2 = T[b2 + i - k - 2];
                float a3 = T[b3 + i - k - 3];
                if (jb >= i && jb < m) {
                    float x = T[bi + jb - i];
                    x -= a0 * t0;
                    x -= a1 * t1;
                    x -= a2 * t2;
                    x -= a3 * t3;
                    T[bi + jb - i] = x;
                }
                bi += m - i;
            }
            basek = b3 + (m - k - 3);
            k += 4;
            __syncwarp();
        }
    } else {
        // ---- dual-column rank-4 panels (m in 34..52) ----
        while (k + 3 < m) {
            int b0 = basek;
            int b1 = b0 + (m - k);
            int b2 = b1 + (m - k - 1);
            int b3 = b2 + (m - k - 2);
            float piv0 = T[b0]; float inv0 = 1.0f / piv0;
            float a01 = T[b0 + 1];
            {
                int jj = k + 1 + lane;
                if (jj < m) {
                    float t = T[b0 + jj - k] * inv0;
                    T[b1 + jj - k - 1] -= a01 * t;
                }
                int j2 = jj + 32;
                if (j2 < m) {
                    float t = T[b0 + j2 - k] * inv0;
                    T[b1 + j2 - k - 1] -= a01 * t;
                }
            }
            __syncwarp();
            float piv1 = T[b1]; float inv1 = 1.0f / piv1;
            float a02 = T[b0 + 2], a12 = T[b1 + 1];
            {
                int jj = k + 2 + lane;
                if (jj < m) {
                    float t0 = T[b0 + jj - k] * inv0;
                    float x = T[b2 + jj - k - 2];
                    x -= a02 * t0;
                    float t1 = T[b1 + jj - k - 1] * inv1;
                    x -= a12 * t1;
                    T[b2 + jj - k - 2] = x;
                }
                int j2 = jj + 32;
                if (j2 < m) {
                    float t0 = T[b0 + j2 - k] * inv0;
                    float x = T[b2 + j2 - k - 2];
                    x -= a02 * t0;
                    float t1 = T[b1 + j2 - k - 1] * inv1;
                    x -= a12 * t1;
                    T[b2 + j2 - k - 2] = x;
                }
            }
            __syncwarp();
            float piv2 = T[b2]; float inv2 = 1.0f / piv2;
            float a03 = T[b0 + 3], a13 = T[b1 + 2], a23 = T[b2 + 1];
            {
                int jj = k + 3 + lane;
                if (jj < m) {
                    float t0 = T[b0 + jj - k] * inv0;
                    float x = T[b3 + jj - k - 3];
                    x -= a03 * t0;
                    float t1 = T[b1 + jj - k - 1] * inv1;
                    x -= a13 * t1;
                    float t2 = T[b2 + jj - k - 2] * inv2;
                    x -= a23 * t2;
                    T[b3 + jj - k - 3] = x;
                }
                int j2 = jj + 32;
                if (j2 < m) {
                    float t0 = T[b0 + j2 - k] * inv0;
                    float x = T[b3 + j2 - k - 3];
                    x -= a03 * t0;
                    float t1 = T[b1 + j2 - k - 1] * inv1;
                    x -= a13 * t1;
                    float t2 = T[b2 + j2 - k - 2] * inv2;
                    x -= a23 * t2;
                    T[b3 + j2 - k - 3] = x;
                }
            }
            __syncwarp();
            float piv3 = T[b3]; float inv3 = 1.0f / piv3;
            if (lane == 0) {
                logA += logf(piv0);
                logA += logf(piv1);
                logA += logf(piv2);
                if (k + 3 < m - 1) logA += logf(piv3);
                else lastpiv = piv3;
            }
            int jb = k + 4 + lane, jb1 = jb + 32;
            float t0 = 0.f, t1 = 0.f, t2 = 0.f, t3 = 0.f;
            float u0 = 0.f, u1 = 0.f, u2 = 0.f, u3 = 0.f;
            if (jb < m) {
                t0 = T[b0 + jb - k] * inv0;
                t1 = T[b1 + jb - k - 1] * inv1;
                t2 = T[b2 + jb - k - 2] * inv2;
                t3 = T[b3 + jb - k - 3] * inv3;
            }
            if (jb1 < m) {
                u0 = T[b0 + jb1 - k] * inv0;
                u1 = T[b1 + jb1 - k - 1] * inv1;
                u2 = T[b2 + jb1 - k - 2] * inv2;
                u3 = T[b3 + jb1 - k - 3] * inv3;
            }
            int bi = b3 + (m - k - 3);
            for (int i = k + 4; i < m; i++) {
                float a0 = T[b0 + i - k];
                float a1 = T[b1 + i - k - 1];
                float a2 = T[b2 + i - k - 2];
                float a3 = T[b3 + i - k - 3];
                if (jb >= i && jb < m) {
                    float x = T[bi + jb - i];
                    x -= a0 * t0;
                    x -= a1 * t1;
                    x -= a2 * t2;
                    x -= a3 * t3;
                    T[bi + jb - i] = x;
                }
                if (jb1 >= i && jb1 < m) {
                    float x = T[bi + jb1 - i];
                    x -= a0 * u0;
                    x -= a1 * u1;
                    x -= a2 * u2;
                    x -= a3 * u3;
                    T[bi + jb1 - i] = x;
                }
                bi += m - i;
            }
            basek = b3 + (m - k - 3);
            k += 4;
            __syncwarp();
        }
    }
    // ---- remainder rows (m - k <= 3): proven rank-1 path ----
    for (; k < m; k++) {
        float piv = T[basek];
        if (lane == 0) {
            if (k < m - 1) logA += logf(piv);
            else lastpiv = piv;
        }
        int rem = m - 1 - k;
        if (rem > 0) {
            float inv = 1.0f / piv;
            int j0 = k + 1 + lane;
            float t0 = (lane < rem) ? T[basek + 1 + lane] * inv : 0.f;
            int bi = basek + (m - k);
            for (int i = k + 1; i < m; i++) {
                float aki = T[basek + i - k];
                if (j0 >= i && j0 < m) T[bi + j0 - i] -= aki * t0;
                bi += m - i;
            }
        }
        basek += m - k;
        __syncwarp();
    }
    if (lane == 0) {
        ns[task] = g_lgtab[l] - 0.5 * (double)logA
                 - 0.5 * (2051.0 + (double)l) * log((double)lastpiv);
    }
}

// ---------------- fallback: BGe big (m > CAP only) ----------------
__global__ void __launch_bounds__(128) bge_big_kernel(
        const unsigned long long* __restrict__ cols,
        double* __restrict__ ns, int ntask) {
    __shared__ float sT[4][2080];
    __shared__ unsigned char sidx[4][64];
    int w = threadIdx.x >> 5, lane = threadIdx.x & 31;
    int task = blockIdx.x * 4 + w;
    if (task >= ntask) return;
    unsigned long long mask = cols[task];
    int l = __popcll(mask);
    int m = l + 1;
    if (m <= CAP) return;
    int j = task & 63;
    unsigned char* idx = sidx[w];
    if (lane == 0) {
        unsigned long long mm = mask; int c = 0;
        while (mm) { int b = __ffsll(mm) - 1; idx[c++] = (unsigned char)b; mm &= mm - 1; }
        idx[l] = (unsigned char)j;
    }
    __syncwarp();
    float* T = sT[w];
    {
        int base = 0;
        for (int a = 0; a < m; a++) {
            const float* Rrow = g_R + (int)idx[a] * 64;
            for (int b = a + lane; b < m; b += 32) T[base + b - a] = Rrow[idx[b]];
            base += m - a;
        }
    }
    __syncwarp();
    float logA = 0.f, lastpiv = 1.f;
    int basek = 0;
    int k = 0;
    for (; k < m - 33; k++) {
        float piv = T[basek];
        if (lane == 0) logA += logf(piv);
        float inv = 1.0f / piv;
        int j0 = k + 1 + lane, j1 = j0 + 32;
        float t0 = T[basek + 1 + lane] * inv;
        float t1 = (j1 < m) ? T[basek + 33 + lane] * inv : 0.f;
        int bi = basek + (m - k);
        for (int i = k + 1; i < m; i++) {
            float aki = T[basek + i - k];
            if (j0 >= i)           T[bi + j0 - i] -= aki * t0;
            if (j1 >= i && j1 < m) T[bi + j1 - i] -= aki * t1;
            bi += m - i;
        }
        basek += m - k;
        __syncwarp();
    }
    for (; k < m; k++) {
        float piv = T[basek];
        if (lane == 0) {
            if (k < m - 1) logA += logf(piv);
            else lastpiv = piv;
        }
        int rem = m - 1 - k;
        if (rem > 0) {
            float inv = 1.0f / piv;
            int j0 = k + 1 + lane;
            float t0 = (lane < rem) ? T[basek + 1 + lane] * inv : 0.f;
            int bi = basek + (m - k);
            for (int i = k + 1; i < m; i++) {
                float aki = T[basek + i - k];
                if (j0 >= i && j0 < m) T[bi + j0 - i] -= aki * t0;
                bi += m - i;
            }
        }
        basek += m - k;
        __syncwarp();
    }
    if (lane == 0) {
        ns[task] = g_lgtab[l] - 0.5 * (double)logA
                 - 0.5 * (2051.0 + (double)l) * log((double)lastpiv);
    }
}

// ---------------- fused reduce + softmax (MC): block per particle ----------------
__global__ void __launch_bounds__(512) redsoft_kernel() {
    __shared__ double sv[16];
    int p = blockIdx.x;
    int s = threadIdx.x >> 5, lane = threadIdx.x & 31;
    const double* nsg = g_ns + (p * 16 + s) * 64;
    double a = nsg[lane] + nsg[lane + 32];
    for (int o = 16; o > 0; o >>= 1) a += __shfl_xor_sync(0xffffffffu, a, o);
    if (lane == 0) sv[s] = a;
    __syncthreads();
    if (threadIdx.x < 32) {
        double v = (lane < 16) ? sv[lane] : -1e300;
        double mx = v;
        for (int o = 16; o > 0; o >>= 1) mx = fmax(mx, __shfl_xor_sync(0xffffffffu, mx, o));
        double e = (lane < 16) ? exp(v - mx) : 0.0;
        double sm = e;
        for (int o = 16; o > 0; o >>= 1) sm += __shfl_xor_sync(0xffffffffu, sm, o);
        if (lane < 16) g_w[p * 16 + lane] = e / sm;
    }
}

// hard graphs: deterministic tree reduce straight into the float output slot
__global__ void reduce64h_kernel(const double* __restrict__ ns, float* __restrict__ out) {
    __shared__ double s[64];
    int g = blockIdx.x, t = threadIdx.x;
    s[t] = ns[g * 64 + t];
    __syncthreads();
    for (int st = 32; st > 0; st >>= 1) {
        if (t < st) s[t] += s[t + st];
        __syncthreads();
    }
    if (t == 0) out[OFF_LOGP + g] = (float)s[0];
}

// ---------------- B ----------------
__global__ void B_kernel() {
    int idx = blockIdx.x * blockDim.x + threadIdx.x;
    int j = idx & 63, i = (idx >> 6) & 63, p = idx >> 12;
    float pr = g_probs[p * 4096 + i * 64 + j];
    double ws = 0.0;
    for (int s = 0; s < 16; s++)
        if ((g_cols[(p * 16 + s) * 64 + j] >> i) & 1ull) ws += g_w[p * 16 + s];
    float B = 0.f;
    if (i != j)
        B = 0.2f * ((float)ws - pr) + 0.2f * pr * (1.f - pr) * (float)g_logitpe;
    g_B[idx] = B;
}

// ---------------- grads (fused u/v) ----------------
__global__ void gradufv_kernel(const float* __restrict__ z) {
    int bb = blockIdx.x;
    int k = threadIdx.x;
    if (bb < 2048) {
        int p = bb >> 6, i = bb & 63;
        const float* Bp = g_B + p * 4096 + i * 64;
        const float* zp = z + p * 8192;
        float acc = 0.f;
        for (int j = 0; j < 64; j++) acc = fmaf(Bp[j], zp[(j * 64 + k) * 2 + 1], acc);
        float u = zp[(i * 64 + k) * 2];
        g_grads[(bb * 64 + k) * 2] = acc - 64.f * u;
    } else {
        int b2 = bb - 2048;
        int p = b2 >> 6, j = b2 & 63;
        const float* Bp = g_B + p * 4096;
        const float* zp = z + p * 8192;
        float acc = 0.f;
        for (int i = 0; i < 64; i++) acc = fmaf(Bp[i * 64 + j], zp[(i * 64 + k) * 2], acc);
        float v = zp[(j * 64 + k) * 2 + 1];
        g_grads[((p * 64 + j) * 64 + k) * 2 + 1] = acc - 64.f * v;
    }
}

// ---------------- SVGD Kmat: f32, warp per pair ----------------
__global__ void __launch_bounds__(128) kmat_kernel(const float* __restrict__ z) {
    int pair = blockIdx.x * 4 + (threadIdx.x >> 5);  // 0..1023
    int lane = threadIdx.x & 31;
    int p = pair >> 5, q = pair & 31;
    const float* a = z + p * 8192;
    const float* b = z + q * 8192;
    float sq0 = 0.f, sq1 = 0.f;
    for (int t = lane; t < 8192; t += 64) {
        float d0 = a[t] - b[t];
        float d1 = a[t + 32] - b[t + 32];
        sq0 = fmaf(d0, d0, sq0);
        sq1 = fmaf(d1, d1, sq1);
    }
    float sq = sq0 + sq1;
    for (int o = 16; o > 0; o >>= 1) sq += __shfl_xor_sync(0xffffffffu, sq, o);
    if (lane == 0) g_Kmat[p * 32 + q] = expf(-sq * 0.2f);
}

__global__ void znew_kernel(const float* __restrict__ z, float* __restrict__ out) {
    int p = blockIdx.x;
    __shared__ float kr[32];
    __shared__ float rowsum;
    if (threadIdx.x < 32) kr[threadIdx.x] = g_Kmat[p * 32 + threadIdx.x];
    __syncthreads();
    if (threadIdx.x == 0) {
        float s = 0.f;
        for (int q = 0; q < 32; q++) s += kr[q];
        rowsum = s;
    }
    __syncthreads();
    for (int d = threadIdx.x; d < 8192; d += blockDim.x) {
        float ag = 0.f, az = 0.f;
        for (int q = 0; q < 32; q++) {
            float kk = kr[q];
            ag = fmaf(kk, g_grads[q * 8192 + d], ag);
            az = fmaf(kk, z[q * 8192 + d], az);
        }
        float zp = z[p * 8192 + d];
        float rep = (-2.0f / 5.0f) * (az - zp * rowsum);
        float zn = zp + 0.005f * ((ag + rep) * (1.0f / 32.0f));
        out[OFF_ZNEW + p * 8192 + d] = zn;
    }
}

// ---------------- hard graphs: ILPx4 (thread=i, 4 j's), ballot masks ----------------
__global__ void s2_kernel(float* __restrict__ out) {
    __shared__ unsigned int mparts[2][4];
    int b = blockIdx.x;
    int p = b >> 4, jg = b & 15;
    int i = threadIdx.x;                 // 0..63, two warps
    const float* zn = out + OFF_ZNEW + p * 8192;
    int j0 = jg * 4;
    double acc0 = 0.0, acc1 = 0.0, acc2 = 0.0, acc3 = 0.0;
    for (int k = 0; k < 64; k++) {
        double ui = (double)zn[(i * 64 + k) * 2];
        acc0 += ui * (double)zn[((j0 + 0) * 64 + k) * 2 + 1];
        acc1 += ui * (double)zn[((j0 + 1) * 64 + k) * 2 + 1];
        acc2 += ui * (double)zn[((j0 + 2) * 64 + k) * 2 + 1];
        acc3 += ui * (double)zn[((j0 + 3) * 64 + k) * 2 + 1];
    }
    double accs[4] = {acc0, acc1, acc2, acc3};
#pragma unroll
    for (int r = 0; r < 4; r++) {
        int j = j0 + r;
        bool edge = (i != j && accs[r] > 0.0);
        out[OFF_GHARD + p * 4096 + i * 64 + j] = edge ? 1.f : 0.f;
        unsigned bal = __ballot_sync(0xffffffffu, edge);
        if ((i & 31) == 0) mparts[i >> 5][r] = bal;
    }
    __syncthreads();
    if (i < 4)
        g_colsh[p * 64 + j0 + i] = (unsigned long long)mparts[0][i]
                                 | ((unsigned long long)mparts[1][i] << 32);
}

// ---------------- encoder L1 ----------------
__global__ void enc0_kernel(const float* __restrict__ out,
                            const float* __restrict__ ew0,
                            const float* __restrict__ eb0) {
    int gw = blockIdx.x * 8 + (threadIdx.x >> 5);
    if (gw >= 640) return;
    int p = gw / 20, o = gw % 20;
    int lane = threadIdx.x & 31;
    const float* gp = out + OFF_GHARD + p * 4096;
    float acc = 0.f;
    for (int t = lane; t < 4096; t += 32) acc = fmaf(gp[t], ew0[t * 20 + o], acc);
    for (int of = 16; of > 0; of >>= 1) acc += __shfl_xor_sync(0xffffffffu, acc, of);
    if (lane == 0) g_h0[p * 20 + o] = fmaxf(0.f, acc + eb0[o]);
}

// ---------------- remaining MLP layers: one block per particle ----------------
__global__ void __launch_bounds__(64) mlp_kernel(float* __restrict__ out,
    const float* ew1, const float* eb1, const float* ew2, const float* eb2,
    const float* mw0, const float* mb0, const float* mw1, const float* mb1,
    const float* lw0, const float* lb0, const float* lw1, const float* lb1,
    const float* dw0, const float* db0, const float* dw1, const float* db1,
    const float* dw2, const float* db2) {
    __shared__ float h0s[20];
    __shared__ float h1[64];
    __shared__ float h2[64];
    __shared__ float amu[64];
    __shared__ float qmu[64];
    __shared__ float alv[64];
    __shared__ float qz[64];
    __shared__ float hd0[10];
    __shared__ float hd1[128];
    int p = blockIdx.x, o = threadIdx.x;
    if (o < 20) h0s[o] = g_h0[p * 20 + o];
    __syncthreads();
    {
        float a = eb1[o];
        for (int t = 0; t < 20; t++) a = fmaf(h0s[t], ew1[t * 64 + o], a);
        h1[o] = fmaxf(0.f, a);
    }
    __syncthreads();
    {
        float a = eb2[o];
        for (int t = 0; t < 64; t++) a = fmaf(h1[t], ew2[t * 64 + o], a);
        h2[o] = fmaxf(0.f, a);
    }
    __syncthreads();
    {
        float a = mb0[o];
        for (int t = 0; t < 64; t++) a = fmaf(h2[t], mw0[t * 64 + o], a);
        amu[o] = fmaxf(0.f, a);
        float b = lb0[o];
        for (int t = 0; t < 64; t++) b = fmaf(h2[t], lw0[t * 64 + o], b);
        alv[o] = fmaxf(0.f, b);
    }
    __syncthreads();
    {
        float a = mb1[o];
        for (int t = 0; t < 64; t++) a = fmaf(amu[t], mw1[t * 64 + o], a);
        qmu[o] = a;
        out[OFF_QMU + p * 64 + o] = a;
        float b = lb1[o];
        for (int t = 0; t < 64; t++) b = fmaf(alv[t], lw1[t * 64 + o], b);
        out[OFF_QLV + p * 64 + o] = b;
        float eps = jax_normal(jax_bits32(g_keys[2], g_keys[3], (unsigned)(p * 64 + o)));
        float q = qmu[o] + eps * expf(0.5f * b);
        out[OFF_QZ + p * 64 + o] = q;
        qz[o] = q;
    }
    __syncthreads();
    if (o < 10) {
        float a = db0[o];
        for (int t = 0; t < 64; t++) a = fmaf(qz[t], dw0[t * 10 + o], a);
        hd0[o] = fmaxf(0.f, a);
    }
    __syncthreads();
#pragma unroll
    for (int g = 0; g < 2; g++) {
        int oo = o + g * 64;
        float a = db1[oo];
        for (int t = 0; t < 10; t++) a = fmaf(hd0[t], dw1[t * 128 + oo], a);
        hd1[oo] = fmaxf(0.f, a);
    }
    __syncthreads();
#pragma unroll
    for (int g = 0; g < 2; g++) {
        int oo = o + g * 64;
        float a = db2[oo];
        for (int t = 0; t < 128; t++) a = fmaf(hd1[t], dw2[t * 128 + oo], a);
        out[OFF_RECONS + p * 128 + oo] = a;
    }
}

// ---------------- launch ----------------
extern "C" void kernel_launch(void* const* d_in, const int* in_sizes, int n_in,
                              void* d_out, int out_size) {
    const float* z_gt = (const float*)d_in[0];
    const float* z0   = (const float*)d_in[1];
    const float* ew0 = (const float*)d_in[2];  const float* eb0 = (const float*)d_in[3];
    const float* ew1 = (const float*)d_in[4];  const float* eb1 = (const float*)d_in[5];
    const float* ew2 = (const float*)d_in[6];  const float* eb2 = (const float*)d_in[7];
    const float* mw0 = (const float*)d_in[8];  const float* mb0 = (const float*)d_in[9];
    const float* mw1 = (const float*)d_in[10]; const float* mb1 = (const float*)d_in[11];
    const float* lw0 = (const float*)d_in[12]; const float* lb0 = (const float*)d_in[13];
    const float* lw1 = (const float*)d_in[14]; const float* lb1 = (const float*)d_in[15];
    const float* dw0 = (const float*)d_in[16]; const float* db0 = (const float*)d_in[17];
    const float* dw1 = (const float*)d_in[18]; const float* db1 = (const float*)d_in[19];
    const float* dw2 = (const float*)d_in[20]; const float* db2 = (const float*)d_in[21];
    const int*   seed = (const int*)d_in[22];
    float* out = (float*)d_out;

    unsigned long long* colsMC; cudaGetSymbolAddress((void**)&colsMC, g_cols);
    unsigned long long* colsH;  cudaGetSymbolAddress((void**)&colsH,  g_colsh);
    double* nsMC;  cudaGetSymbolAddress((void**)&nsMC,  g_ns);
    double* nsH;   cudaGetSymbolAddress((void**)&nsH,   g_nsh);

    scores_kernel<<<512, 64>>>(z0, z_gt, seed);                // 1: probs + xbar + init
    Rtile_kernel<<<16, 256>>>(z_gt);                           // 2: R partials
    bern_kernel<<<1024, 256>>>();                              // 3: sampling + R finalize
    bge_small_kernel<<<NG * 64 / 8, 256>>>(colsMC, nsMC, NG * 64);  // 4 (profiled)
    bge_big_kernel<<<NG * 64 / 4, 128>>>(colsMC, nsMC, NG * 64);
    redsoft_kernel<<<Pn, 512>>>();
    B_kernel<<<512, 256>>>();
    gradufv_kernel<<<4096, 64>>>(z0);
    kmat_kernel<<<256, 128>>>(z0);
    znew_kernel<<<Pn, 256>>>(z0, out);
    s2_kernel<<<512, 64>>>(out);
    bge_small_kernel<<<Pn * 64 / 8, 256>>>(colsH, nsH, Pn * 64);
    bge_big_kernel<<<Pn * 64 / 4, 128>>>(colsH, nsH, Pn * 64);
    reduce64h_kernel<<<Pn, 64>>>(nsH, out);
    enc0_kernel<<<80, 256>>>(out, ew0, eb0);
    mlp_kernel<<<Pn, 64>>>(out, ew1, eb1, ew2, eb2,
                           mw0, mb0, mw1, mb1, lw0, lb0, lw1, lb1,
                           dw0, db0, dw1, db1, dw2, db2);
}